// round 8
// baseline (speedup 1.0000x reference)
#include <cuda_runtime.h>
#include <cuda_bf16.h>
#include <math.h>
#include <stdint.h>

#define BB 32
#define SS 196
#define TT 64
#define HH 1024
#define VV 32000
#define MT (BB * TT)     // 2048
#define KG 2048          // gates K
#define NG 4096          // gates N

// ---------------- device scratch ----------------
__device__ float g_h[BB * HH];
__device__ float g_c[BB * HH];
__device__ float g_sc[BB * SS];
__device__ float g_M2[(size_t)BB * SS * HH];
__device__ float g_P[(size_t)MT * NG];
__device__ float g_gpart[(size_t)8 * BB * NG];
__device__ float g_biasg[NG];
__device__ float g_zeroN[VV];
__device__ __align__(16) __nv_bfloat16 g_Wh[(size_t)VV * HH], g_Wl[(size_t)VV * HH];
__device__ __align__(16) __nv_bfloat16 g_Ah[(size_t)MT * HH], g_Al[(size_t)MT * HH];
__device__ __align__(16) __nv_bfloat16 g_Memh[(size_t)BB * SS * HH], g_Meml[(size_t)BB * SS * HH];
__device__ __align__(16) __nv_bfloat16 g_Wth[(size_t)HH * HH], g_Wtl[(size_t)HH * HH];
__device__ __align__(16) __nv_bfloat16 g_WihAh[(size_t)NG * HH], g_WihAl[(size_t)NG * HH];
__device__ __align__(16) __nv_bfloat16 g_Wgh[(size_t)NG * KG], g_Wgl[(size_t)NG * KG];
__device__ __align__(16) __nv_bfloat16 g_Embh[(size_t)MT * HH], g_Embl[(size_t)MT * HH];
__device__ __align__(16) __nv_bfloat16 g_Xh[128 * KG], g_Xl[128 * KG];   // rows 32..127 stay zero

__device__ __forceinline__ float sigmoidf_(float x) { return 1.f / (1.f + expf(-x)); }
__device__ __forceinline__ void bsplit(float w, __nv_bfloat16& hi, __nv_bfloat16& lo) {
    hi = __float2bfloat16_rn(w);
    lo = __float2bfloat16_rn(w - __bfloat162float(hi));
}
__device__ __forceinline__ void split8(const float* __restrict__ src,
                                       __nv_bfloat16* __restrict__ dh,
                                       __nv_bfloat16* __restrict__ dl) {
    float4 v0 = *(const float4*)src;
    float4 v1 = *(const float4*)(src + 4);
    float f[8] = {v0.x, v0.y, v0.z, v0.w, v1.x, v1.y, v1.z, v1.w};
    __align__(16) __nv_bfloat16 h[8];
    __align__(16) __nv_bfloat16 l[8];
#pragma unroll
    for (int k = 0; k < 8; k++) bsplit(f[k], h[k], l[k]);
    *(uint4*)dh = *(const uint4*)h;
    *(uint4*)dl = *(const uint4*)l;
}

__device__ __forceinline__ uint32_t smem_u32(const void* p) {
    uint32_t a;
    asm("{ .reg .u64 t; cvta.to.shared.u64 t, %1; cvt.u32.u64 %0, t; }" : "=r"(a) : "l"(p));
    return a;
}
__device__ __forceinline__ void cp16(uint32_t s, const void* g) {
    asm volatile("cp.async.cg.shared.global [%0], [%1], 16;" :: "r"(s), "l"(g));
}
__device__ __forceinline__ void ldm_x4(uint32_t* r, uint32_t addr) {
    asm volatile("ldmatrix.sync.aligned.m8n8.x4.shared.b16 {%0,%1,%2,%3}, [%4];"
                 : "=r"(r[0]), "=r"(r[1]), "=r"(r[2]), "=r"(r[3]) : "r"(addr));
}
__device__ __forceinline__ void mma_bf16(float* c, const uint32_t* a, const uint32_t* b) {
    asm volatile("mma.sync.aligned.m16n8k16.row.col.f32.bf16.bf16.f32 "
                 "{%0,%1,%2,%3}, {%4,%5,%6,%7}, {%8,%9}, {%0,%1,%2,%3};"
                 : "+f"(c[0]), "+f"(c[1]), "+f"(c[2]), "+f"(c[3])
                 : "r"(a[0]), "r"(a[1]), "r"(a[2]), "r"(a[3]), "r"(b[0]), "r"(b[1]));
}

// ================= init / split kernels =================
__global__ void k_init(const float* __restrict__ b_ih, const float* __restrict__ b_hh) {
    int i = blockIdx.x * blockDim.x + threadIdx.x;   // 1024 x 256 = 262144
    __nv_bfloat16 z = __float2bfloat16(0.f);
    if (i < 128 * KG) { g_Xh[i] = z; g_Xl[i] = z; }
    if (i < BB * HH) { g_h[i] = 0.f; g_c[i] = 0.f; }
    if (i < BB * SS) g_sc[i] = 0.f;                  // h0 = 0 -> scores_0 = 0
    if (i < VV) g_zeroN[i] = 0.f;
    if (i < NG) g_biasg[i] = b_ih[i] + b_hh[i];
}

__global__ void k_splitW8(const float* __restrict__ W) {
    size_t i = ((size_t)blockIdx.x * blockDim.x + threadIdx.x) * 8;
    if (i < (size_t)VV * HH) split8(W + i, g_Wh + i, g_Wl + i);
}
__global__ void k_splitWg8(const float* __restrict__ W_ih, const float* __restrict__ W_hh) {
    size_t i = ((size_t)blockIdx.x * blockDim.x + threadIdx.x) * 8;
    if (i < (size_t)NG * KG) {
        size_t n = i >> 11;
        int k = (int)(i & 2047);
        const float* src = (k < HH) ? (W_ih + n * (2 * HH) + HH + k)
                                    : (W_hh + n * HH + (k - HH));
        split8(src, g_Wgh + i, g_Wgl + i);
    }
}
__global__ void k_splitWihA8(const float* __restrict__ W_ih) {
    size_t i = ((size_t)blockIdx.x * blockDim.x + threadIdx.x) * 8;
    if (i < (size_t)NG * HH) {
        size_t n = i >> 10;
        int k = (int)(i & 1023);
        split8(W_ih + n * (2 * HH) + k, g_WihAh + i, g_WihAl + i);
    }
}
__global__ void k_splitMem8(const float* __restrict__ memory) {
    size_t i = ((size_t)blockIdx.x * blockDim.x + threadIdx.x) * 8;
    if (i < (size_t)BB * SS * HH) split8(memory + i, g_Memh + i, g_Meml + i);
}
__global__ void k_splitEmb8(const int* __restrict__ captions, const float* __restrict__ emb_table) {
    size_t i = ((size_t)blockIdx.x * blockDim.x + threadIdx.x) * 8;
    if (i < (size_t)MT * HH) {
        int m = (int)(i >> 10);
        int k = (int)(i & 1023);
        split8(emb_table + (size_t)captions[m] * HH + k, g_Embh + i, g_Embl + i);
    }
}
// Wt[n][j] = attn_W[j][n]
__global__ void k_splitWt(const float* __restrict__ W) {
    __shared__ float tile[32][33];
    int jb = blockIdx.x * 32, nb = blockIdx.y * 32;
    int tx = threadIdx.x & 31, ty = threadIdx.x >> 5;
#pragma unroll
    for (int r = 0; r < 32; r += 8)
        tile[ty + r][tx] = W[(size_t)(jb + ty + r) * HH + nb + tx];
    __syncthreads();
#pragma unroll
    for (int r = 0; r < 32; r += 8) {
        size_t o = (size_t)(nb + ty + r) * HH + jb + tx;
        bsplit(tile[tx][ty + r], g_Wth[o], g_Wtl[o]);
    }
}

// ================= generic 3-pass HMMA core (BM=BN=128, 256 thr, optional k-split) =================
#define LTILE (128 * 144)           // 18432 B
#define LSTAGE (4 * LTILE)          // 73728 B
#define LSMEM (2 * LSTAGE)          // 147456 B

__device__ __forceinline__ void gemm_core(
    const __nv_bfloat16* __restrict__ Ah, const __nv_bfloat16* __restrict__ Al,
    const __nv_bfloat16* __restrict__ Bh, const __nv_bfloat16* __restrict__ Bl,
    const float* __restrict__ bias, float* __restrict__ out,
    size_t ldout, int Ktot, int mlimit, size_t pstride)
{
    extern __shared__ char smem[];
    uint32_t sb = smem_u32(smem);
    int tid = threadIdx.x, wid = tid >> 5, lane = tid & 31;
    int wm = wid >> 2, wn = wid & 3;
    int bm = blockIdx.x, bn = blockIdx.y, ks = blockIdx.z;
    int Kper = Ktot / (int)gridDim.z;
    int chunks = Kper >> 6;
    int kbeg = ks * Kper;

    const __nv_bfloat16* gA[4];
    gA[0] = Ah + (size_t)bm * 128 * Ktot + kbeg;
    gA[1] = Al + (size_t)bm * 128 * Ktot + kbeg;
    gA[2] = Bh + (size_t)bn * 128 * Ktot + kbeg;
    gA[3] = Bl + (size_t)bn * 128 * Ktot + kbeg;

    float acc[4][4][4];
#pragma unroll
    for (int i = 0; i < 4; i++)
#pragma unroll
        for (int j = 0; j < 4; j++)
#pragma unroll
            for (int k = 0; k < 4; k++) acc[i][j][k] = 0.f;

    int lrow = tid >> 3, lc4 = tid & 7;

#pragma unroll
    for (int t = 0; t < 4; t++) {
        uint32_t base = sb + t * LTILE;
#pragma unroll
        for (int r4 = 0; r4 < 4; r4++) {
            int row = lrow + r4 * 32;
            cp16(base + row * 144 + lc4 * 16, gA[t] + (size_t)row * Ktot + lc4 * 8);
        }
    }
    asm volatile("cp.async.commit_group;");

    for (int ch = 0; ch < chunks; ch++) {
        int st = ch & 1;
        if (ch < chunks - 1) {
            int k0 = (ch + 1) * 64;
            uint32_t stb = sb + ((ch + 1) & 1) * LSTAGE;
#pragma unroll
            for (int t = 0; t < 4; t++) {
                uint32_t base = stb + t * LTILE;
#pragma unroll
                for (int r4 = 0; r4 < 4; r4++) {
                    int row = lrow + r4 * 32;
                    cp16(base + row * 144 + lc4 * 16, gA[t] + (size_t)row * Ktot + k0 + lc4 * 8);
                }
            }
            asm volatile("cp.async.commit_group;");
            asm volatile("cp.async.wait_group 1;");
        } else {
            asm volatile("cp.async.wait_group 0;");
        }
        __syncthreads();

        uint32_t sAh = sb + st * LSTAGE;
        uint32_t sAl = sAh + LTILE;
        uint32_t sBh = sAh + 2 * LTILE;
        uint32_t sBl = sAh + 3 * LTILE;

#pragma unroll
        for (int k16 = 0; k16 < 4; k16++) {
            int kc = k16 * 16;
            uint32_t bh[4][2], bl[4][2];
#pragma unroll
            for (int j2 = 0; j2 < 2; j2++) {
                int nrow = wn * 32 + j2 * 16 + ((lane >> 4) << 3) + (lane & 7);
                int kcol = kc + (lane & 8);
                uint32_t r[4];
                ldm_x4(r, sBh + nrow * 144 + kcol * 2);
                bh[j2 * 2][0] = r[0]; bh[j2 * 2][1] = r[1];
                bh[j2 * 2 + 1][0] = r[2]; bh[j2 * 2 + 1][1] = r[3];
                ldm_x4(r, sBl + nrow * 144 + kcol * 2);
                bl[j2 * 2][0] = r[0]; bl[j2 * 2][1] = r[1];
                bl[j2 * 2 + 1][0] = r[2]; bl[j2 * 2 + 1][1] = r[3];
            }
#pragma unroll
            for (int i = 0; i < 4; i++) {
                int arow = wm * 64 + i * 16 + (lane & 15);
                int acol = kc + ((lane >> 4) << 3);
                uint32_t ah[4], al[4];
                ldm_x4(ah, sAh + arow * 144 + acol * 2);
                ldm_x4(al, sAl + arow * 144 + acol * 2);
#pragma unroll
                for (int j = 0; j < 4; j++) mma_bf16(acc[i][j], ah, bh[j]);
#pragma unroll
                for (int j = 0; j < 4; j++) mma_bf16(acc[i][j], ah, bl[j]);
#pragma unroll
                for (int j = 0; j < 4; j++) mma_bf16(acc[i][j], al, bh[j]);
            }
        }
        __syncthreads();
    }

    float* outp = out + (size_t)ks * pstride;
#pragma unroll
    for (int i = 0; i < 4; i++) {
        int row0 = bm * 128 + wm * 64 + i * 16 + (lane >> 2);
#pragma unroll
        for (int j = 0; j < 4; j++) {
            int col = bn * 128 + wn * 32 + j * 8 + (lane & 3) * 2;
            float2 bv = *(const float2*)(bias + col);
            if (row0 < mlimit)
                *(float2*)(outp + (size_t)row0 * ldout + col) =
                    make_float2(acc[i][j][0] + bv.x, acc[i][j][1] + bv.y);
            if (row0 + 8 < mlimit)
                *(float2*)(outp + (size_t)(row0 + 8) * ldout + col) =
                    make_float2(acc[i][j][2] + bv.x, acc[i][j][3] + bv.y);
        }
    }
}

__global__ __launch_bounds__(256, 1) void k_gemm_M2() {
    gemm_core(g_Memh, g_Meml, g_Wth, g_Wtl, g_zeroN, g_M2, HH, HH, 1 << 30, 0);
}
__global__ __launch_bounds__(256, 1) void k_gemm_P() {
    gemm_core(g_Embh, g_Embl, g_WihAh, g_WihAl, g_biasg, g_P, NG, HH, 1 << 30, 0);
}
__global__ __launch_bounds__(256, 1) void k_gemm_G() {
    gemm_core(g_Xh, g_Xl, g_Wgh, g_Wgl, g_zeroN, g_gpart, NG, KG, BB, (size_t)BB * NG);
}
__global__ __launch_bounds__(256, 1) void k_gemm_L(const float* __restrict__ bout,
                                                   float* __restrict__ out) {
    gemm_core(g_Ah, g_Al, g_Wh, g_Wl, bout, out, VV, HH, 1 << 30, 0);
}

// ================= per-step kernels =================
// softmax (recomputed per block) + ctx; writes bf16 split of ctx into X[:, 0:H]
__global__ void k_ctx2(const float* __restrict__ memory) {
    int b = blockIdx.y;
    int tid = threadIdx.x;
    __shared__ float w[SS];
    __shared__ float red[256];

    float v = (tid < SS) ? g_sc[b * SS + tid] : -1e30f;
    red[tid] = v;
    __syncthreads();
    for (int o = 128; o > 0; o >>= 1) {
        if (tid < o) red[tid] = fmaxf(red[tid], red[tid + o]);
        __syncthreads();
    }
    float mx = red[0];
    __syncthreads();
    float e = (tid < SS) ? expf(v - mx) : 0.f;
    if (tid < SS) w[tid] = e;
    red[tid] = e;
    __syncthreads();
    for (int o = 128; o > 0; o >>= 1) {
        if (tid < o) red[tid] += red[tid + o];
        __syncthreads();
    }
    float inv = 1.f / red[0];
    __syncthreads();

    int hcol = blockIdx.x * 256 + tid;
    const float* mb = memory + (size_t)b * SS * HH + hcol;
    float a0 = 0.f, a1 = 0.f, a2 = 0.f, a3 = 0.f;
    int s = 0;
    for (; s + 8 <= SS; s += 8) {
        float m0 = mb[(size_t)(s + 0) * HH], m1 = mb[(size_t)(s + 1) * HH];
        float m2 = mb[(size_t)(s + 2) * HH], m3 = mb[(size_t)(s + 3) * HH];
        float m4 = mb[(size_t)(s + 4) * HH], m5 = mb[(size_t)(s + 5) * HH];
        float m6 = mb[(size_t)(s + 6) * HH], m7 = mb[(size_t)(s + 7) * HH];
        a0 += w[s + 0] * m0; a1 += w[s + 1] * m1; a2 += w[s + 2] * m2; a3 += w[s + 3] * m3;
        a0 += w[s + 4] * m4; a1 += w[s + 5] * m5; a2 += w[s + 6] * m6; a3 += w[s + 7] * m7;
    }
    {
        float m0 = mb[(size_t)(s + 0) * HH], m1 = mb[(size_t)(s + 1) * HH];
        float m2 = mb[(size_t)(s + 2) * HH], m3 = mb[(size_t)(s + 3) * HH];
        a0 += w[s + 0] * m0; a1 += w[s + 1] * m1; a2 += w[s + 2] * m2; a3 += w[s + 3] * m3;
    }
    float cv = (a0 + a1 + a2 + a3) * inv;
    __nv_bfloat16 hi, lo;
    bsplit(cv, hi, lo);
    g_Xh[b * KG + hcol] = hi;
    g_Xl[b * KG + hcol] = lo;
}

// fused LSTM cell (step t) + scores for step t+1. grid = BB blocks x 1024 thr.
// Single writer per b for g_c (one block owns batch row b) -> no double buffer.
__global__ __launch_bounds__(1024) void k_cellscores(int t) {
    int b = blockIdx.x;
    int tid = threadIdx.x, wid = tid >> 5, lane = tid & 31;
    __shared__ float hs[HH];

    // ---- cell for (b, j = tid) ----
    int j = tid;
    size_t pr = ((size_t)b * TT + t) * NG;
    float a0 = g_P[pr + j];
    float a1 = g_P[pr + HH + j];
    float a2 = g_P[pr + 2 * HH + j];
    float a3 = g_P[pr + 3 * HH + j];
#pragma unroll
    for (int z = 0; z < 8; z++) {
        const float* gp = g_gpart + ((size_t)z * BB + b) * NG;
        a0 += gp[j];
        a1 += gp[HH + j];
        a2 += gp[2 * HH + j];
        a3 += gp[3 * HH + j];
    }
    float gi = sigmoidf_(a0);
    float gf = sigmoidf_(a1);
    float gg = tanhf(a2);
    float go = sigmoidf_(a3);
    float cp = g_c[b * HH + j];
    float cn = gf * cp + gi * gg;
    float hn = go * tanhf(cn);
    g_c[b * HH + j] = cn;
    hs[j] = hn;
    __nv_bfloat16 hi, lo;
    bsplit(hn, hi, lo);
    g_Xh[b * KG + HH + j] = hi;
    g_Xl[b * KG + HH + j] = lo;
    size_t ar = ((size_t)b * TT + t) * HH + j;
    g_Ah[ar] = hi;
    g_Al[ar] = lo;
    __syncthreads();

    // ---- scores for step t+1: 32 warps over 196 s, float4 loads ----
    const float4* hs4 = (const float4*)hs;
    for (int s = wid; s < SS; s += 32) {
        const float4* mr4 = (const float4*)(g_M2 + ((size_t)b * SS + s) * HH);
        float acc = 0.f;
#pragma unroll
        for (int k = 0; k < 2; k++) {
            int k0 = lane + k * 128;
            float4 m0 = mr4[k0],      m1 = mr4[k0 + 32];
            float4 m2 = mr4[k0 + 64], m3 = mr4[k0 + 96];
            float4 h0 = hs4[k0],      h1 = hs4[k0 + 32];
            float4 h2 = hs4[k0 + 64], h3 = hs4[k0 + 96];
            acc += m0.x * h0.x + m0.y * h0.y + m0.z * h0.z + m0.w * h0.w;
            acc += m1.x * h1.x + m1.y * h1.y + m1.z * h1.z + m1.w * h1.w;
            acc += m2.x * h2.x + m2.y * h2.y + m2.z * h2.z + m2.w * h2.w;
            acc += m3.x * h3.x + m3.y * h3.y + m3.z * h3.z + m3.w * h3.w;
        }
#pragma unroll
        for (int o = 16; o > 0; o >>= 1) acc += __shfl_xor_sync(0xffffffffu, acc, o);
        if (lane == 0) g_sc[b * SS + s] = acc;
    }
}

// final cell (t=63): writes g_h, g_c, Ah/Al row 63
__global__ void k_cellfin() {
    int i = blockIdx.x * blockDim.x + threadIdx.x;
    int b = i >> 10, j = i & 1023;
    size_t pr = ((size_t)b * TT + 63) * NG;
    float a0 = g_P[pr + j];
    float a1 = g_P[pr + HH + j];
    float a2 = g_P[pr + 2 * HH + j];
    float a3 = g_P[pr + 3 * HH + j];
#pragma unroll
    for (int z = 0; z < 8; z++) {
        const float* gp = g_gpart + ((size_t)z * BB + b) * NG;
        a0 += gp[j];
        a1 += gp[HH + j];
        a2 += gp[2 * HH + j];
        a3 += gp[3 * HH + j];
    }
    float gi = sigmoidf_(a0);
    float gf = sigmoidf_(a1);
    float gg = tanhf(a2);
    float go = sigmoidf_(a3);
    float cn = gf * g_c[i] + gi * gg;
    float hn = go * tanhf(cn);
    g_c[i] = cn;
    g_h[i] = hn;
    __nv_bfloat16 hi, lo;
    bsplit(hn, hi, lo);
    size_t ar = ((size_t)b * TT + 63) * HH + j;
    g_Ah[ar] = hi;
    g_Al[ar] = lo;
}

// ================= output final h, c =================
__global__ void k_final(float* __restrict__ out) {
    int i = blockIdx.x * blockDim.x + threadIdx.x;
    if (i < BB * HH) {
        size_t base = (size_t)BB * TT * VV;
        out[base + i] = g_h[i];
        out[base + BB * HH + i] = g_c[i];
    }
}

// ---------------- launch ----------------
extern "C" void kernel_launch(void* const* d_in, const int* in_sizes, int n_in,
                              void* d_out, int out_size) {
    const float* memory    = (const float*)d_in[0];
    const int*   captions  = (const int*)d_in[1];
    const float* emb_table = (const float*)d_in[2];
    const float* attn_W    = (const float*)d_in[3];
    const float* W_ih      = (const float*)d_in[4];
    const float* W_hh      = (const float*)d_in[5];
    const float* b_ih      = (const float*)d_in[6];
    const float* b_hh      = (const float*)d_in[7];
    const float* W_out     = (const float*)d_in[8];
    const float* b_out     = (const float*)d_in[9];
    float* out = (float*)d_out;

    static int inited = 0;
    if (!inited) {
        cudaFuncSetAttribute(k_gemm_M2, cudaFuncAttributeMaxDynamicSharedMemorySize, LSMEM);
        cudaFuncSetAttribute(k_gemm_P,  cudaFuncAttributeMaxDynamicSharedMemorySize, LSMEM);
        cudaFuncSetAttribute(k_gemm_G,  cudaFuncAttributeMaxDynamicSharedMemorySize, LSMEM);
        cudaFuncSetAttribute(k_gemm_L,  cudaFuncAttributeMaxDynamicSharedMemorySize, LSMEM);
        inited = 1;
    }

    k_init<<<1024, 256>>>(b_ih, b_hh);
    k_splitW8<<<(int)(((size_t)VV * HH / 8 + 255) / 256), 256>>>(W_out);
    k_splitWg8<<<(int)(((size_t)NG * KG / 8 + 255) / 256), 256>>>(W_ih, W_hh);
    k_splitWihA8<<<(int)(((size_t)NG * HH / 8 + 255) / 256), 256>>>(W_ih);
    k_splitMem8<<<(int)(((size_t)BB * SS * HH / 8 + 255) / 256), 256>>>(memory);
    k_splitEmb8<<<(int)(((size_t)MT * HH / 8 + 255) / 256), 256>>>(captions, emb_table);
    k_splitWt<<<dim3(HH / 32, HH / 32), 256>>>(attn_W);

    k_gemm_M2<<<dim3(BB * SS / 128, HH / 128, 1), 256, LSMEM>>>();
    k_gemm_P<<<dim3(MT / 128, NG / 128, 1), 256, LSMEM>>>();

    for (int t = 0; t < TT; t++) {
        k_ctx2<<<dim3(4, BB), 256>>>(memory);
        k_gemm_G<<<dim3(1, NG / 128, 8), 256, LSMEM>>>();
        if (t < TT - 1) k_cellscores<<<BB, 1024>>>(t);
        else            k_cellfin<<<128, 256>>>();
    }

    k_gemm_L<<<dim3(MT / 128, VV / 128, 1), 256, LSMEM>>>(b_out, out);
    k_final<<<128, 256>>>(out);
}

// round 9
// speedup vs baseline: 1.1160x; 1.1160x over previous
#include <cuda_runtime.h>
#include <cuda_bf16.h>
#include <math.h>
#include <stdint.h>

#define BB 32
#define SS 196
#define TT 64
#define HH 1024
#define VV 32000
#define MT (BB * TT)     // 2048
#define KG 2048          // gates K
#define NG 4096          // gates N

// ---------------- device scratch ----------------
__device__ float g_h[BB * HH];
__device__ float g_c[BB * HH];
__device__ float g_sc[BB * SS];
__device__ float g_M2[(size_t)BB * SS * HH];
__device__ float g_P[(size_t)MT * NG];
__device__ float g_gpart[(size_t)8 * BB * NG];
__device__ float g_biasg[NG];
__device__ float g_zeroN[VV];
__device__ __align__(16) __nv_bfloat16 g_Wh[(size_t)VV * HH], g_Wl[(size_t)VV * HH];
__device__ __align__(16) __nv_bfloat16 g_Ah[(size_t)MT * HH], g_Al[(size_t)MT * HH];
__device__ __align__(16) __nv_bfloat16 g_Memh[(size_t)BB * SS * HH], g_Meml[(size_t)BB * SS * HH];
__device__ __align__(16) __nv_bfloat16 g_Wth[(size_t)HH * HH], g_Wtl[(size_t)HH * HH];
__device__ __align__(16) __nv_bfloat16 g_WihAh[(size_t)NG * HH], g_WihAl[(size_t)NG * HH];
__device__ __align__(16) __nv_bfloat16 g_Wgh[(size_t)NG * KG], g_Wgl[(size_t)NG * KG];
__device__ __align__(16) __nv_bfloat16 g_Embh[(size_t)MT * HH], g_Embl[(size_t)MT * HH];
__device__ __align__(16) __nv_bfloat16 g_Xh[32 * KG], g_Xl[32 * KG];

__device__ __forceinline__ float sigmoidf_(float x) { return 1.f / (1.f + expf(-x)); }
__device__ __forceinline__ void bsplit(float w, __nv_bfloat16& hi, __nv_bfloat16& lo) {
    hi = __float2bfloat16_rn(w);
    lo = __float2bfloat16_rn(w - __bfloat162float(hi));
}
__device__ __forceinline__ void split8(const float* __restrict__ src,
                                       __nv_bfloat16* __restrict__ dh,
                                       __nv_bfloat16* __restrict__ dl) {
    float4 v0 = *(const float4*)src;
    float4 v1 = *(const float4*)(src + 4);
    float f[8] = {v0.x, v0.y, v0.z, v0.w, v1.x, v1.y, v1.z, v1.w};
    __align__(16) __nv_bfloat16 h[8];
    __align__(16) __nv_bfloat16 l[8];
#pragma unroll
    for (int k = 0; k < 8; k++) bsplit(f[k], h[k], l[k]);
    *(uint4*)dh = *(const uint4*)h;
    *(uint4*)dl = *(const uint4*)l;
}

__device__ __forceinline__ uint32_t smem_u32(const void* p) {
    uint32_t a;
    asm("{ .reg .u64 t; cvta.to.shared.u64 t, %1; cvt.u32.u64 %0, t; }" : "=r"(a) : "l"(p));
    return a;
}
__device__ __forceinline__ void cp16(uint32_t s, const void* g) {
    asm volatile("cp.async.cg.shared.global [%0], [%1], 16;" :: "r"(s), "l"(g));
}
__device__ __forceinline__ void ldm_x4(uint32_t* r, uint32_t addr) {
    asm volatile("ldmatrix.sync.aligned.m8n8.x4.shared.b16 {%0,%1,%2,%3}, [%4];"
                 : "=r"(r[0]), "=r"(r[1]), "=r"(r[2]), "=r"(r[3]) : "r"(addr));
}
__device__ __forceinline__ void mma_bf16(float* c, const uint32_t* a, const uint32_t* b) {
    asm volatile("mma.sync.aligned.m16n8k16.row.col.f32.bf16.bf16.f32 "
                 "{%0,%1,%2,%3}, {%4,%5,%6,%7}, {%8,%9}, {%0,%1,%2,%3};"
                 : "+f"(c[0]), "+f"(c[1]), "+f"(c[2]), "+f"(c[3])
                 : "r"(a[0]), "r"(a[1]), "r"(a[2]), "r"(a[3]), "r"(b[0]), "r"(b[1]));
}

// ================= init / split kernels =================
__global__ void k_init(const float* __restrict__ b_ih, const float* __restrict__ b_hh) {
    int i = blockIdx.x * blockDim.x + threadIdx.x;
    __nv_bfloat16 z = __float2bfloat16(0.f);
    if (i < 32 * KG) { g_Xh[i] = z; g_Xl[i] = z; }
    if (i < BB * HH) { g_h[i] = 0.f; g_c[i] = 0.f; }
    if (i < BB * SS) g_sc[i] = 0.f;                  // h0 = 0 -> scores_0 = 0
    if (i < VV) g_zeroN[i] = 0.f;
    if (i < NG) g_biasg[i] = b_ih[i] + b_hh[i];
}

__global__ void k_splitW8(const float* __restrict__ W) {
    size_t i = ((size_t)blockIdx.x * blockDim.x + threadIdx.x) * 8;
    if (i < (size_t)VV * HH) split8(W + i, g_Wh + i, g_Wl + i);
}
__global__ void k_splitWg8(const float* __restrict__ W_ih, const float* __restrict__ W_hh) {
    size_t i = ((size_t)blockIdx.x * blockDim.x + threadIdx.x) * 8;
    if (i < (size_t)NG * KG) {
        size_t n = i >> 11;
        int k = (int)(i & 2047);
        const float* src = (k < HH) ? (W_ih + n * (2 * HH) + HH + k)
                                    : (W_hh + n * HH + (k - HH));
        split8(src, g_Wgh + i, g_Wgl + i);
    }
}
__global__ void k_splitWihA8(const float* __restrict__ W_ih) {
    size_t i = ((size_t)blockIdx.x * blockDim.x + threadIdx.x) * 8;
    if (i < (size_t)NG * HH) {
        size_t n = i >> 10;
        int k = (int)(i & 1023);
        split8(W_ih + n * (2 * HH) + k, g_WihAh + i, g_WihAl + i);
    }
}
__global__ void k_splitMem8(const float* __restrict__ memory) {
    size_t i = ((size_t)blockIdx.x * blockDim.x + threadIdx.x) * 8;
    if (i < (size_t)BB * SS * HH) split8(memory + i, g_Memh + i, g_Meml + i);
}
__global__ void k_splitEmb8(const int* __restrict__ captions, const float* __restrict__ emb_table) {
    size_t i = ((size_t)blockIdx.x * blockDim.x + threadIdx.x) * 8;
    if (i < (size_t)MT * HH) {
        int m = (int)(i >> 10);
        int k = (int)(i & 1023);
        split8(emb_table + (size_t)captions[m] * HH + k, g_Embh + i, g_Embl + i);
    }
}
// Wt[n][j] = attn_W[j][n]
__global__ void k_splitWt(const float* __restrict__ W) {
    __shared__ float tile[32][33];
    int jb = blockIdx.x * 32, nb = blockIdx.y * 32;
    int tx = threadIdx.x & 31, ty = threadIdx.x >> 5;
#pragma unroll
    for (int r = 0; r < 32; r += 8)
        tile[ty + r][tx] = W[(size_t)(jb + ty + r) * HH + nb + tx];
    __syncthreads();
#pragma unroll
    for (int r = 0; r < 32; r += 8) {
        size_t o = (size_t)(nb + ty + r) * HH + jb + tx;
        bsplit(tile[tx][ty + r], g_Wth[o], g_Wtl[o]);
    }
}

// ================= generic 3-pass HMMA core (BM=BN=128, 256 thr) =================
#define LTILE (128 * 144)           // 18432 B
#define LSTAGE (4 * LTILE)          // 73728 B
#define LSMEM (2 * LSTAGE)          // 147456 B

__device__ __forceinline__ void gemm_core(
    const __nv_bfloat16* __restrict__ Ah, const __nv_bfloat16* __restrict__ Al,
    const __nv_bfloat16* __restrict__ Bh, const __nv_bfloat16* __restrict__ Bl,
    const float* __restrict__ bias, float* __restrict__ out,
    size_t ldout, int Ktot)
{
    extern __shared__ char smem[];
    uint32_t sb = smem_u32(smem);
    int tid = threadIdx.x, wid = tid >> 5, lane = tid & 31;
    int wm = wid >> 2, wn = wid & 3;
    int bm = blockIdx.x, bn = blockIdx.y;
    int chunks = Ktot >> 6;

    const __nv_bfloat16* gA[4];
    gA[0] = Ah + (size_t)bm * 128 * Ktot;
    gA[1] = Al + (size_t)bm * 128 * Ktot;
    gA[2] = Bh + (size_t)bn * 128 * Ktot;
    gA[3] = Bl + (size_t)bn * 128 * Ktot;

    float acc[4][4][4];
#pragma unroll
    for (int i = 0; i < 4; i++)
#pragma unroll
        for (int j = 0; j < 4; j++)
#pragma unroll
            for (int k = 0; k < 4; k++) acc[i][j][k] = 0.f;

    int lrow = tid >> 3, lc4 = tid & 7;

#pragma unroll
    for (int t = 0; t < 4; t++) {
        uint32_t base = sb + t * LTILE;
#pragma unroll
        for (int r4 = 0; r4 < 4; r4++) {
            int row = lrow + r4 * 32;
            cp16(base + row * 144 + lc4 * 16, gA[t] + (size_t)row * Ktot + lc4 * 8);
        }
    }
    asm volatile("cp.async.commit_group;");

    for (int ch = 0; ch < chunks; ch++) {
        int st = ch & 1;
        if (ch < chunks - 1) {
            int k0 = (ch + 1) * 64;
            uint32_t stb = sb + ((ch + 1) & 1) * LSTAGE;
#pragma unroll
            for (int t = 0; t < 4; t++) {
                uint32_t base = stb + t * LTILE;
#pragma unroll
                for (int r4 = 0; r4 < 4; r4++) {
                    int row = lrow + r4 * 32;
                    cp16(base + row * 144 + lc4 * 16, gA[t] + (size_t)row * Ktot + k0 + lc4 * 8);
                }
            }
            asm volatile("cp.async.commit_group;");
            asm volatile("cp.async.wait_group 1;");
        } else {
            asm volatile("cp.async.wait_group 0;");
        }
        __syncthreads();

        uint32_t sAh = sb + st * LSTAGE;
        uint32_t sAl = sAh + LTILE;
        uint32_t sBh = sAh + 2 * LTILE;
        uint32_t sBl = sAh + 3 * LTILE;

#pragma unroll
        for (int k16 = 0; k16 < 4; k16++) {
            int kc = k16 * 16;
            uint32_t bh[4][2], bl[4][2];
#pragma unroll
            for (int j2 = 0; j2 < 2; j2++) {
                int nrow = wn * 32 + j2 * 16 + ((lane >> 4) << 3) + (lane & 7);
                int kcol = kc + (lane & 8);
                uint32_t r[4];
                ldm_x4(r, sBh + nrow * 144 + kcol * 2);
                bh[j2 * 2][0] = r[0]; bh[j2 * 2][1] = r[1];
                bh[j2 * 2 + 1][0] = r[2]; bh[j2 * 2 + 1][1] = r[3];
                ldm_x4(r, sBl + nrow * 144 + kcol * 2);
                bl[j2 * 2][0] = r[0]; bl[j2 * 2][1] = r[1];
                bl[j2 * 2 + 1][0] = r[2]; bl[j2 * 2 + 1][1] = r[3];
            }
#pragma unroll
            for (int i = 0; i < 4; i++) {
                int arow = wm * 64 + i * 16 + (lane & 15);
                int acol = kc + ((lane >> 4) << 3);
                uint32_t ah[4], al[4];
                ldm_x4(ah, sAh + arow * 144 + acol * 2);
                ldm_x4(al, sAl + arow * 144 + acol * 2);
#pragma unroll
                for (int j = 0; j < 4; j++) mma_bf16(acc[i][j], ah, bh[j]);
#pragma unroll
                for (int j = 0; j < 4; j++) mma_bf16(acc[i][j], ah, bl[j]);
#pragma unroll
                for (int j = 0; j < 4; j++) mma_bf16(acc[i][j], al, bh[j]);
            }
        }
        __syncthreads();
    }

#pragma unroll
    for (int i = 0; i < 4; i++) {
        int row0 = bm * 128 + wm * 64 + i * 16 + (lane >> 2);
#pragma unroll
        for (int j = 0; j < 4; j++) {
            int col = bn * 128 + wn * 32 + j * 8 + (lane & 3) * 2;
            float2 bv = *(const float2*)(bias + col);
            *(float2*)(out + (size_t)row0 * ldout + col) =
                make_float2(acc[i][j][0] + bv.x, acc[i][j][1] + bv.y);
            *(float2*)(out + (size_t)(row0 + 8) * ldout + col) =
                make_float2(acc[i][j][2] + bv.x, acc[i][j][3] + bv.y);
        }
    }
}

__global__ __launch_bounds__(256, 1) void k_gemm_M2() {
    gemm_core(g_Memh, g_Meml, g_Wth, g_Wtl, g_zeroN, g_M2, HH, HH);
}
__global__ __launch_bounds__(256, 1) void k_gemm_P() {
    gemm_core(g_Embh, g_Embl, g_WihAh, g_WihAl, g_biasg, g_P, NG, HH);
}
__global__ __launch_bounds__(256, 1) void k_gemm_L(const float* __restrict__ bout,
                                                   float* __restrict__ out) {
    gemm_core(g_Ah, g_Al, g_Wh, g_Wl, bout, out, VV, HH);
}

// ================= gates GEMM: BM=32 (exact M), BN=128, 256 thr, k-split 8 =================
// R6-proven correct. 92 KB smem -> 2 blocks/SM; 256 blocks = 1 wave at occ 2.
#define GT_A (32 * 144)                 // 4608
#define GT_B (128 * 144)                // 18432
#define GOFF_AL GT_A
#define GOFF_BH (2 * GT_A)
#define GOFF_BL (2 * GT_A + GT_B)
#define GSTG (2 * GT_A + 2 * GT_B)      // 46080
#define GSMEM (2 * GSTG)                // 92160

__global__ __launch_bounds__(256, 2) void k_gates_s() {
    extern __shared__ char smem[];
    uint32_t sb = smem_u32(smem);
    int tid = threadIdx.x, wid = tid >> 5, lane = tid & 31;
    int wm = wid >> 2, wn = wid & 3;     // 2 x 4, warp tile 16x32
    int bn = blockIdx.x, ks = blockIdx.y;
    int kbeg = ks * 256;

    const __nv_bfloat16* gAh = g_Xh + kbeg;
    const __nv_bfloat16* gAl = g_Xl + kbeg;
    const __nv_bfloat16* gBh = g_Wgh + (size_t)bn * 128 * KG + kbeg;
    const __nv_bfloat16* gBl = g_Wgl + (size_t)bn * 128 * KG + kbeg;

    float acc[4][4];
#pragma unroll
    for (int j = 0; j < 4; j++)
#pragma unroll
        for (int k = 0; k < 4; k++) acc[j][k] = 0.f;

    int lrow = tid >> 3, lc4 = tid & 7;  // lrow 0..31

    {
        cp16(sb + lrow * 144 + lc4 * 16, gAh + (size_t)lrow * KG + lc4 * 8);
        cp16(sb + GOFF_AL + lrow * 144 + lc4 * 16, gAl + (size_t)lrow * KG + lc4 * 8);
#pragma unroll
        for (int r4 = 0; r4 < 4; r4++) {
            int row = lrow + r4 * 32;
            cp16(sb + GOFF_BH + row * 144 + lc4 * 16, gBh + (size_t)row * KG + lc4 * 8);
            cp16(sb + GOFF_BL + row * 144 + lc4 * 16, gBl + (size_t)row * KG + lc4 * 8);
        }
        asm volatile("cp.async.commit_group;");
    }

    for (int ch = 0; ch < 4; ch++) {
        int st = ch & 1;
        if (ch < 3) {
            int k0 = (ch + 1) * 64;
            uint32_t stb = sb + ((ch + 1) & 1) * GSTG;
            cp16(stb + lrow * 144 + lc4 * 16, gAh + (size_t)lrow * KG + k0 + lc4 * 8);
            cp16(stb + GOFF_AL + lrow * 144 + lc4 * 16, gAl + (size_t)lrow * KG + k0 + lc4 * 8);
#pragma unroll
            for (int r4 = 0; r4 < 4; r4++) {
                int row = lrow + r4 * 32;
                cp16(stb + GOFF_BH + row * 144 + lc4 * 16, gBh + (size_t)row * KG + k0 + lc4 * 8);
                cp16(stb + GOFF_BL + row * 144 + lc4 * 16, gBl + (size_t)row * KG + k0 + lc4 * 8);
            }
            asm volatile("cp.async.commit_group;");
            asm volatile("cp.async.wait_group 1;");
        } else {
            asm volatile("cp.async.wait_group 0;");
        }
        __syncthreads();

        uint32_t sAh = sb + st * GSTG;
        uint32_t sAl = sAh + GOFF_AL;
        uint32_t sBh = sAh + GOFF_BH;
        uint32_t sBl = sAh + GOFF_BL;

#pragma unroll
        for (int k16 = 0; k16 < 4; k16++) {
            int kc = k16 * 16;
            uint32_t bh[4][2], bl[4][2];
#pragma unroll
            for (int j2 = 0; j2 < 2; j2++) {
                int nrow = wn * 32 + j2 * 16 + ((lane >> 4) << 3) + (lane & 7);
                int kcol = kc + (lane & 8);
                uint32_t r[4];
                ldm_x4(r, sBh + nrow * 144 + kcol * 2);
                bh[j2 * 2][0] = r[0]; bh[j2 * 2][1] = r[1];
                bh[j2 * 2 + 1][0] = r[2]; bh[j2 * 2 + 1][1] = r[3];
                ldm_x4(r, sBl + nrow * 144 + kcol * 2);
                bl[j2 * 2][0] = r[0]; bl[j2 * 2][1] = r[1];
                bl[j2 * 2 + 1][0] = r[2]; bl[j2 * 2 + 1][1] = r[3];
            }
            int arow = wm * 16 + (lane & 15);
            int acol = kc + ((lane >> 4) << 3);
            uint32_t ah[4], al[4];
            ldm_x4(ah, sAh + arow * 144 + acol * 2);
            ldm_x4(al, sAl + arow * 144 + acol * 2);
#pragma unroll
            for (int j = 0; j < 4; j++) mma_bf16(acc[j], ah, bh[j]);
#pragma unroll
            for (int j = 0; j < 4; j++) mma_bf16(acc[j], ah, bl[j]);
#pragma unroll
            for (int j = 0; j < 4; j++) mma_bf16(acc[j], al, bh[j]);
        }
        __syncthreads();
    }

    float* outp = g_gpart + (size_t)ks * BB * NG;
    int row0 = wm * 16 + (lane >> 2);
#pragma unroll
    for (int j = 0; j < 4; j++) {
        int col = bn * 128 + wn * 32 + j * 8 + (lane & 3) * 2;
        *(float2*)(outp + (size_t)row0 * NG + col) = make_float2(acc[j][0], acc[j][1]);
        *(float2*)(outp + (size_t)(row0 + 8) * NG + col) = make_float2(acc[j][2], acc[j][3]);
    }
}

// ================= per-step kernels =================
__global__ void k_ctx2(const float* __restrict__ memory) {
    int b = blockIdx.y;
    int tid = threadIdx.x;
    __shared__ float w[SS];
    __shared__ float red[256];

    float v = (tid < SS) ? g_sc[b * SS + tid] : -1e30f;
    red[tid] = v;
    __syncthreads();
    for (int o = 128; o > 0; o >>= 1) {
        if (tid < o) red[tid] = fmaxf(red[tid], red[tid + o]);
        __syncthreads();
    }
    float mx = red[0];
    __syncthreads();
    float e = (tid < SS) ? expf(v - mx) : 0.f;
    if (tid < SS) w[tid] = e;
    red[tid] = e;
    __syncthreads();
    for (int o = 128; o > 0; o >>= 1) {
        if (tid < o) red[tid] += red[tid + o];
        __syncthreads();
    }
    float inv = 1.f / red[0];
    __syncthreads();

    int hcol = blockIdx.x * 256 + tid;
    const float* mb = memory + (size_t)b * SS * HH + hcol;
    float a0 = 0.f, a1 = 0.f, a2 = 0.f, a3 = 0.f;
    int s = 0;
    for (; s + 8 <= SS; s += 8) {
        float m0 = mb[(size_t)(s + 0) * HH], m1 = mb[(size_t)(s + 1) * HH];
        float m2 = mb[(size_t)(s + 2) * HH], m3 = mb[(size_t)(s + 3) * HH];
        float m4 = mb[(size_t)(s + 4) * HH], m5 = mb[(size_t)(s + 5) * HH];
        float m6 = mb[(size_t)(s + 6) * HH], m7 = mb[(size_t)(s + 7) * HH];
        a0 += w[s + 0] * m0; a1 += w[s + 1] * m1; a2 += w[s + 2] * m2; a3 += w[s + 3] * m3;
        a0 += w[s + 4] * m4; a1 += w[s + 5] * m5; a2 += w[s + 6] * m6; a3 += w[s + 7] * m7;
    }
    {
        float m0 = mb[(size_t)(s + 0) * HH], m1 = mb[(size_t)(s + 1) * HH];
        float m2 = mb[(size_t)(s + 2) * HH], m3 = mb[(size_t)(s + 3) * HH];
        a0 += w[s + 0] * m0; a1 += w[s + 1] * m1; a2 += w[s + 2] * m2; a3 += w[s + 3] * m3;
    }
    float cv = (a0 + a1 + a2 + a3) * inv;
    __nv_bfloat16 hi, lo;
    bsplit(cv, hi, lo);
    g_Xh[b * KG + hcol] = hi;
    g_Xl[b * KG + hcol] = lo;
}

// fused LSTM cell (step t) + scores for step t+1. grid = BB blocks x 1024 thr.
__global__ __launch_bounds__(1024) void k_cellscores(int t) {
    int b = blockIdx.x;
    int tid = threadIdx.x, wid = tid >> 5, lane = tid & 31;
    __shared__ float hs[HH];

    int j = tid;
    size_t pr = ((size_t)b * TT + t) * NG;
    float a0 = g_P[pr + j];
    float a1 = g_P[pr + HH + j];
    float a2 = g_P[pr + 2 * HH + j];
    float a3 = g_P[pr + 3 * HH + j];
#pragma unroll
    for (int z = 0; z < 8; z++) {
        const float* gp = g_gpart + ((size_t)z * BB + b) * NG;
        a0 += gp[j];
        a1 += gp[HH + j];
        a2 += gp[2 * HH + j];
        a3 += gp[3 * HH + j];
    }
    float gi = sigmoidf_(a0);
    float gf = sigmoidf_(a1);
    float gg = tanhf(a2);
    float go = sigmoidf_(a3);
    float cp = g_c[b * HH + j];
    float cn = gf * cp + gi * gg;
    float hn = go * tanhf(cn);
    g_c[b * HH + j] = cn;
    hs[j] = hn;
    __nv_bfloat16 hi, lo;
    bsplit(hn, hi, lo);
    g_Xh[b * KG + HH + j] = hi;
    g_Xl[b * KG + HH + j] = lo;
    size_t ar = ((size_t)b * TT + t) * HH + j;
    g_Ah[ar] = hi;
    g_Al[ar] = lo;
    __syncthreads();

    const float4* hs4 = (const float4*)hs;
    for (int s = wid; s < SS; s += 32) {
        const float4* mr4 = (const float4*)(g_M2 + ((size_t)b * SS + s) * HH);
        float acc = 0.f;
#pragma unroll
        for (int k = 0; k < 2; k++) {
            int k0 = lane + k * 128;
            float4 m0 = mr4[k0],      m1 = mr4[k0 + 32];
            float4 m2 = mr4[k0 + 64], m3 = mr4[k0 + 96];
            float4 h0 = hs4[k0],      h1 = hs4[k0 + 32];
            float4 h2 = hs4[k0 + 64], h3 = hs4[k0 + 96];
            acc += m0.x * h0.x + m0.y * h0.y + m0.z * h0.z + m0.w * h0.w;
            acc += m1.x * h1.x + m1.y * h1.y + m1.z * h1.z + m1.w * h1.w;
            acc += m2.x * h2.x + m2.y * h2.y + m2.z * h2.z + m2.w * h2.w;
            acc += m3.x * h3.x + m3.y * h3.y + m3.z * h3.z + m3.w * h3.w;
        }
#pragma unroll
        for (int o = 16; o > 0; o >>= 1) acc += __shfl_xor_sync(0xffffffffu, acc, o);
        if (lane == 0) g_sc[b * SS + s] = acc;
    }
}

// final cell (t=63)
__global__ void k_cellfin() {
    int i = blockIdx.x * blockDim.x + threadIdx.x;
    int b = i >> 10, j = i & 1023;
    size_t pr = ((size_t)b * TT + 63) * NG;
    float a0 = g_P[pr + j];
    float a1 = g_P[pr + HH + j];
    float a2 = g_P[pr + 2 * HH + j];
    float a3 = g_P[pr + 3 * HH + j];
#pragma unroll
    for (int z = 0; z < 8; z++) {
        const float* gp = g_gpart + ((size_t)z * BB + b) * NG;
        a0 += gp[j];
        a1 += gp[HH + j];
        a2 += gp[2 * HH + j];
        a3 += gp[3 * HH + j];
    }
    float gi = sigmoidf_(a0);
    float gf = sigmoidf_(a1);
    float gg = tanhf(a2);
    float go = sigmoidf_(a3);
    float cn = gf * g_c[i] + gi * gg;
    float hn = go * tanhf(cn);
    g_c[i] = cn;
    g_h[i] = hn;
    __nv_bfloat16 hi, lo;
    bsplit(hn, hi, lo);
    size_t ar = ((size_t)b * TT + 63) * HH + j;
    g_Ah[ar] = hi;
    g_Al[ar] = lo;
}

// ================= output final h, c =================
__global__ void k_final(float* __restrict__ out) {
    int i = blockIdx.x * blockDim.x + threadIdx.x;
    if (i < BB * HH) {
        size_t base = (size_t)BB * TT * VV;
        out[base + i] = g_h[i];
        out[base + BB * HH + i] = g_c[i];
    }
}

// ---------------- launch ----------------
extern "C" void kernel_launch(void* const* d_in, const int* in_sizes, int n_in,
                              void* d_out, int out_size) {
    const float* memory    = (const float*)d_in[0];
    const int*   captions  = (const int*)d_in[1];
    const float* emb_table = (const float*)d_in[2];
    const float* attn_W    = (const float*)d_in[3];
    const float* W_ih      = (const float*)d_in[4];
    const float* W_hh      = (const float*)d_in[5];
    const float* b_ih      = (const float*)d_in[6];
    const float* b_hh      = (const float*)d_in[7];
    const float* W_out     = (const float*)d_in[8];
    const float* b_out     = (const float*)d_in[9];
    float* out = (float*)d_out;

    static int inited = 0;
    if (!inited) {
        cudaFuncSetAttribute(k_gemm_M2, cudaFuncAttributeMaxDynamicSharedMemorySize, LSMEM);
        cudaFuncSetAttribute(k_gemm_P,  cudaFuncAttributeMaxDynamicSharedMemorySize, LSMEM);
        cudaFuncSetAttribute(k_gates_s, cudaFuncAttributeMaxDynamicSharedMemorySize, GSMEM);
        cudaFuncSetAttribute(k_gemm_L,  cudaFuncAttributeMaxDynamicSharedMemorySize, LSMEM);
        inited = 1;
    }

    k_init<<<1024, 256>>>(b_ih, b_hh);
    k_splitW8<<<(int)(((size_t)VV * HH / 8 + 255) / 256), 256>>>(W_out);
    k_splitWg8<<<(int)(((size_t)NG * KG / 8 + 255) / 256), 256>>>(W_ih, W_hh);
    k_splitWihA8<<<(int)(((size_t)NG * HH / 8 + 255) / 256), 256>>>(W_ih);
    k_splitMem8<<<(int)(((size_t)BB * SS * HH / 8 + 255) / 256), 256>>>(memory);
    k_splitEmb8<<<(int)(((size_t)MT * HH / 8 + 255) / 256), 256>>>(captions, emb_table);
    k_splitWt<<<dim3(HH / 32, HH / 32), 256>>>(attn_W);

    k_gemm_M2<<<dim3(BB * SS / 128, HH / 128), 256, LSMEM>>>();
    k_gemm_P<<<dim3(MT / 128, NG / 128), 256, LSMEM>>>();

    for (int t = 0; t < TT; t++) {
        k_ctx2<<<dim3(4, BB), 256>>>(memory);
        k_gates_s<<<dim3(NG / 128, 8), 256, GSMEM>>>();
        if (t < TT - 1) k_cellscores<<<BB, 1024>>>(t);
        else            k_cellfin<<<128, 256>>>();
    }

    k_gemm_L<<<dim3(MT / 128, VV / 128), 256, LSMEM>>>(b_out, out);
    k_final<<<128, 256>>>(out);
}

// round 10
// speedup vs baseline: 1.2188x; 1.0921x over previous
#include <cuda_runtime.h>
#include <cuda_bf16.h>
#include <math.h>
#include <stdint.h>

#define BB 32
#define SS 196
#define TT 64
#define HH 1024
#define VV 32000
#define MT (BB * TT)     // 2048
#define KG 2048          // gates K
#define NG 4096          // gates N

// ---------------- device scratch ----------------
__device__ float g_h[BB * HH];
__device__ float g_c[BB * HH];
__device__ float g_M2[(size_t)BB * SS * HH];
__device__ float g_P[(size_t)MT * NG];
__device__ float g_gpart[(size_t)8 * BB * NG];
__device__ float g_biasg[NG];
__device__ float g_zeroN[VV];
__device__ __align__(16) __nv_bfloat16 g_Wh[(size_t)VV * HH], g_Wl[(size_t)VV * HH];
__device__ __align__(16) __nv_bfloat16 g_Ah[(size_t)MT * HH], g_Al[(size_t)MT * HH];
__device__ __align__(16) __nv_bfloat16 g_Memh[(size_t)BB * SS * HH], g_Meml[(size_t)BB * SS * HH];
__device__ __align__(16) __nv_bfloat16 g_Wth[(size_t)HH * HH], g_Wtl[(size_t)HH * HH];
__device__ __align__(16) __nv_bfloat16 g_WihAh[(size_t)NG * HH], g_WihAl[(size_t)NG * HH];
__device__ __align__(16) __nv_bfloat16 g_Wgh[(size_t)NG * KG], g_Wgl[(size_t)NG * KG];
__device__ __align__(16) __nv_bfloat16 g_Embh[(size_t)MT * HH], g_Embl[(size_t)MT * HH];
__device__ __align__(16) __nv_bfloat16 g_Xh[32 * KG], g_Xl[32 * KG];

__device__ __forceinline__ float sigmoidf_(float x) { return 1.f / (1.f + expf(-x)); }
__device__ __forceinline__ void bsplit(float w, __nv_bfloat16& hi, __nv_bfloat16& lo) {
    hi = __float2bfloat16_rn(w);
    lo = __float2bfloat16_rn(w - __bfloat162float(hi));
}
__device__ __forceinline__ void split8(const float* __restrict__ src,
                                       __nv_bfloat16* __restrict__ dh,
                                       __nv_bfloat16* __restrict__ dl) {
    float4 v0 = *(const float4*)src;
    float4 v1 = *(const float4*)(src + 4);
    float f[8] = {v0.x, v0.y, v0.z, v0.w, v1.x, v1.y, v1.z, v1.w};
    __align__(16) __nv_bfloat16 h[8];
    __align__(16) __nv_bfloat16 l[8];
#pragma unroll
    for (int k = 0; k < 8; k++) bsplit(f[k], h[k], l[k]);
    *(uint4*)dh = *(const uint4*)h;
    *(uint4*)dl = *(const uint4*)l;
}

__device__ __forceinline__ uint32_t smem_u32(const void* p) {
    uint32_t a;
    asm("{ .reg .u64 t; cvta.to.shared.u64 t, %1; cvt.u32.u64 %0, t; }" : "=r"(a) : "l"(p));
    return a;
}
__device__ __forceinline__ void cp16(uint32_t s, const void* g) {
    asm volatile("cp.async.cg.shared.global [%0], [%1], 16;" :: "r"(s), "l"(g));
}
__device__ __forceinline__ void ldm_x4(uint32_t* r, uint32_t addr) {
    asm volatile("ldmatrix.sync.aligned.m8n8.x4.shared.b16 {%0,%1,%2,%3}, [%4];"
                 : "=r"(r[0]), "=r"(r[1]), "=r"(r[2]), "=r"(r[3]) : "r"(addr));
}
__device__ __forceinline__ void mma_bf16(float* c, const uint32_t* a, const uint32_t* b) {
    asm volatile("mma.sync.aligned.m16n8k16.row.col.f32.bf16.bf16.f32 "
                 "{%0,%1,%2,%3}, {%4,%5,%6,%7}, {%8,%9}, {%0,%1,%2,%3};"
                 : "+f"(c[0]), "+f"(c[1]), "+f"(c[2]), "+f"(c[3])
                 : "r"(a[0]), "r"(a[1]), "r"(a[2]), "r"(a[3]), "r"(b[0]), "r"(b[1]));
}

// ================= init / split kernels =================
__global__ void k_init(const float* __restrict__ b_ih, const float* __restrict__ b_hh) {
    int i = blockIdx.x * blockDim.x + threadIdx.x;
    __nv_bfloat16 z = __float2bfloat16(0.f);
    if (i < 32 * KG) { g_Xh[i] = z; g_Xl[i] = z; }
    if (i < BB * HH) { g_h[i] = 0.f; g_c[i] = 0.f; }
    if (i < VV) g_zeroN[i] = 0.f;
    if (i < NG) g_biasg[i] = b_ih[i] + b_hh[i];
}

__global__ void k_splitW8(const float* __restrict__ W) {
    size_t i = ((size_t)blockIdx.x * blockDim.x + threadIdx.x) * 8;
    if (i < (size_t)VV * HH) split8(W + i, g_Wh + i, g_Wl + i);
}
__global__ void k_splitWg8(const float* __restrict__ W_ih, const float* __restrict__ W_hh) {
    size_t i = ((size_t)blockIdx.x * blockDim.x + threadIdx.x) * 8;
    if (i < (size_t)NG * KG) {
        size_t n = i >> 11;
        int k = (int)(i & 2047);
        const float* src = (k < HH) ? (W_ih + n * (2 * HH) + HH + k)
                                    : (W_hh + n * HH + (k - HH));
        split8(src, g_Wgh + i, g_Wgl + i);
    }
}
__global__ void k_splitWihA8(const float* __restrict__ W_ih) {
    size_t i = ((size_t)blockIdx.x * blockDim.x + threadIdx.x) * 8;
    if (i < (size_t)NG * HH) {
        size_t n = i >> 10;
        int k = (int)(i & 1023);
        split8(W_ih + n * (2 * HH) + k, g_WihAh + i, g_WihAl + i);
    }
}
__global__ void k_splitMem8(const float* __restrict__ memory) {
    size_t i = ((size_t)blockIdx.x * blockDim.x + threadIdx.x) * 8;
    if (i < (size_t)BB * SS * HH) split8(memory + i, g_Memh + i, g_Meml + i);
}
__global__ void k_splitEmb8(const int* __restrict__ captions, const float* __restrict__ emb_table) {
    size_t i = ((size_t)blockIdx.x * blockDim.x + threadIdx.x) * 8;
    if (i < (size_t)MT * HH) {
        int m = (int)(i >> 10);
        int k = (int)(i & 1023);
        split8(emb_table + (size_t)captions[m] * HH + k, g_Embh + i, g_Embl + i);
    }
}
// Wt[n][j] = attn_W[j][n]
__global__ void k_splitWt(const float* __restrict__ W) {
    __shared__ float tile[32][33];
    int jb = blockIdx.x * 32, nb = blockIdx.y * 32;
    int tx = threadIdx.x & 31, ty = threadIdx.x >> 5;
#pragma unroll
    for (int r = 0; r < 32; r += 8)
        tile[ty + r][tx] = W[(size_t)(jb + ty + r) * HH + nb + tx];
    __syncthreads();
#pragma unroll
    for (int r = 0; r < 32; r += 8) {
        size_t o = (size_t)(nb + ty + r) * HH + jb + tx;
        bsplit(tile[tx][ty + r], g_Wth[o], g_Wtl[o]);
    }
}

// ================= generic 3-pass HMMA core (BM=BN=128, 256 thr) =================
#define LTILE (128 * 144)           // 18432 B
#define LSTAGE (4 * LTILE)          // 73728 B
#define LSMEM (2 * LSTAGE)          // 147456 B

__device__ __forceinline__ void gemm_core(
    const __nv_bfloat16* __restrict__ Ah, const __nv_bfloat16* __restrict__ Al,
    const __nv_bfloat16* __restrict__ Bh, const __nv_bfloat16* __restrict__ Bl,
    const float* __restrict__ bias, float* __restrict__ out,
    size_t ldout, int Ktot)
{
    extern __shared__ char smem[];
    uint32_t sb = smem_u32(smem);
    int tid = threadIdx.x, wid = tid >> 5, lane = tid & 31;
    int wm = wid >> 2, wn = wid & 3;
    int bm = blockIdx.x, bn = blockIdx.y;
    int chunks = Ktot >> 6;

    const __nv_bfloat16* gA[4];
    gA[0] = Ah + (size_t)bm * 128 * Ktot;
    gA[1] = Al + (size_t)bm * 128 * Ktot;
    gA[2] = Bh + (size_t)bn * 128 * Ktot;
    gA[3] = Bl + (size_t)bn * 128 * Ktot;

    float acc[4][4][4];
#pragma unroll
    for (int i = 0; i < 4; i++)
#pragma unroll
        for (int j = 0; j < 4; j++)
#pragma unroll
            for (int k = 0; k < 4; k++) acc[i][j][k] = 0.f;

    int lrow = tid >> 3, lc4 = tid & 7;

#pragma unroll
    for (int t = 0; t < 4; t++) {
        uint32_t base = sb + t * LTILE;
#pragma unroll
        for (int r4 = 0; r4 < 4; r4++) {
            int row = lrow + r4 * 32;
            cp16(base + row * 144 + lc4 * 16, gA[t] + (size_t)row * Ktot + lc4 * 8);
        }
    }
    asm volatile("cp.async.commit_group;");

    for (int ch = 0; ch < chunks; ch++) {
        int st = ch & 1;
        if (ch < chunks - 1) {
            int k0 = (ch + 1) * 64;
            uint32_t stb = sb + ((ch + 1) & 1) * LSTAGE;
#pragma unroll
            for (int t = 0; t < 4; t++) {
                uint32_t base = stb + t * LTILE;
#pragma unroll
                for (int r4 = 0; r4 < 4; r4++) {
                    int row = lrow + r4 * 32;
                    cp16(base + row * 144 + lc4 * 16, gA[t] + (size_t)row * Ktot + k0 + lc4 * 8);
                }
            }
            asm volatile("cp.async.commit_group;");
            asm volatile("cp.async.wait_group 1;");
        } else {
            asm volatile("cp.async.wait_group 0;");
        }
        __syncthreads();

        uint32_t sAh = sb + st * LSTAGE;
        uint32_t sAl = sAh + LTILE;
        uint32_t sBh = sAh + 2 * LTILE;
        uint32_t sBl = sAh + 3 * LTILE;

#pragma unroll
        for (int k16 = 0; k16 < 4; k16++) {
            int kc = k16 * 16;
            uint32_t bh[4][2], bl[4][2];
#pragma unroll
            for (int j2 = 0; j2 < 2; j2++) {
                int nrow = wn * 32 + j2 * 16 + ((lane >> 4) << 3) + (lane & 7);
                int kcol = kc + (lane & 8);
                uint32_t r[4];
                ldm_x4(r, sBh + nrow * 144 + kcol * 2);
                bh[j2 * 2][0] = r[0]; bh[j2 * 2][1] = r[1];
                bh[j2 * 2 + 1][0] = r[2]; bh[j2 * 2 + 1][1] = r[3];
                ldm_x4(r, sBl + nrow * 144 + kcol * 2);
                bl[j2 * 2][0] = r[0]; bl[j2 * 2][1] = r[1];
                bl[j2 * 2 + 1][0] = r[2]; bl[j2 * 2 + 1][1] = r[3];
            }
#pragma unroll
            for (int i = 0; i < 4; i++) {
                int arow = wm * 64 + i * 16 + (lane & 15);
                int acol = kc + ((lane >> 4) << 3);
                uint32_t ah[4], al[4];
                ldm_x4(ah, sAh + arow * 144 + acol * 2);
                ldm_x4(al, sAl + arow * 144 + acol * 2);
#pragma unroll
                for (int j = 0; j < 4; j++) mma_bf16(acc[i][j], ah, bh[j]);
#pragma unroll
                for (int j = 0; j < 4; j++) mma_bf16(acc[i][j], ah, bl[j]);
#pragma unroll
                for (int j = 0; j < 4; j++) mma_bf16(acc[i][j], al, bh[j]);
            }
        }
        __syncthreads();
    }

#pragma unroll
    for (int i = 0; i < 4; i++) {
        int row0 = bm * 128 + wm * 64 + i * 16 + (lane >> 2);
#pragma unroll
        for (int j = 0; j < 4; j++) {
            int col = bn * 128 + wn * 32 + j * 8 + (lane & 3) * 2;
            float2 bv = *(const float2*)(bias + col);
            *(float2*)(out + (size_t)row0 * ldout + col) =
                make_float2(acc[i][j][0] + bv.x, acc[i][j][1] + bv.y);
            *(float2*)(out + (size_t)(row0 + 8) * ldout + col) =
                make_float2(acc[i][j][2] + bv.x, acc[i][j][3] + bv.y);
        }
    }
}

__global__ __launch_bounds__(256, 1) void k_gemm_M2() {
    gemm_core(g_Memh, g_Meml, g_Wth, g_Wtl, g_zeroN, g_M2, HH, HH);
}
__global__ __launch_bounds__(256, 1) void k_gemm_P() {
    gemm_core(g_Embh, g_Embl, g_WihAh, g_WihAl, g_biasg, g_P, NG, HH);
}
__global__ __launch_bounds__(256, 1) void k_gemm_L(const float* __restrict__ bout,
                                                   float* __restrict__ out) {
    gemm_core(g_Ah, g_Al, g_Wh, g_Wl, bout, out, VV, HH);
}

// ================= gates GEMM: BM=32 (exact M), BN=128, 256 thr, k-split 8 =================
#define GT_A (32 * 144)                 // 4608
#define GT_B (128 * 144)                // 18432
#define GOFF_AL GT_A
#define GOFF_BH (2 * GT_A)
#define GOFF_BL (2 * GT_A + GT_B)
#define GSTG (2 * GT_A + 2 * GT_B)      // 46080
#define GSMEM (2 * GSTG)                // 92160

__global__ __launch_bounds__(256, 2) void k_gates_s() {
    extern __shared__ char smem[];
    uint32_t sb = smem_u32(smem);
    int tid = threadIdx.x, wid = tid >> 5, lane = tid & 31;
    int wm = wid >> 2, wn = wid & 3;     // 2 x 4, warp tile 16x32
    int bn = blockIdx.x, ks = blockIdx.y;
    int kbeg = ks * 256;

    const __nv_bfloat16* gAh = g_Xh + kbeg;
    const __nv_bfloat16* gAl = g_Xl + kbeg;
    const __nv_bfloat16* gBh = g_Wgh + (size_t)bn * 128 * KG + kbeg;
    const __nv_bfloat16* gBl = g_Wgl + (size_t)bn * 128 * KG + kbeg;

    float acc[4][4];
#pragma unroll
    for (int j = 0; j < 4; j++)
#pragma unroll
        for (int k = 0; k < 4; k++) acc[j][k] = 0.f;

    int lrow = tid >> 3, lc4 = tid & 7;  // lrow 0..31

    {
        cp16(sb + lrow * 144 + lc4 * 16, gAh + (size_t)lrow * KG + lc4 * 8);
        cp16(sb + GOFF_AL + lrow * 144 + lc4 * 16, gAl + (size_t)lrow * KG + lc4 * 8);
#pragma unroll
        for (int r4 = 0; r4 < 4; r4++) {
            int row = lrow + r4 * 32;
            cp16(sb + GOFF_BH + row * 144 + lc4 * 16, gBh + (size_t)row * KG + lc4 * 8);
            cp16(sb + GOFF_BL + row * 144 + lc4 * 16, gBl + (size_t)row * KG + lc4 * 8);
        }
        asm volatile("cp.async.commit_group;");
    }

    for (int ch = 0; ch < 4; ch++) {
        int st = ch & 1;
        if (ch < 3) {
            int k0 = (ch + 1) * 64;
            uint32_t stb = sb + ((ch + 1) & 1) * GSTG;
            cp16(stb + lrow * 144 + lc4 * 16, gAh + (size_t)lrow * KG + k0 + lc4 * 8);
            cp16(stb + GOFF_AL + lrow * 144 + lc4 * 16, gAl + (size_t)lrow * KG + k0 + lc4 * 8);
#pragma unroll
            for (int r4 = 0; r4 < 4; r4++) {
                int row = lrow + r4 * 32;
                cp16(stb + GOFF_BH + row * 144 + lc4 * 16, gBh + (size_t)row * KG + k0 + lc4 * 8);
                cp16(stb + GOFF_BL + row * 144 + lc4 * 16, gBl + (size_t)row * KG + k0 + lc4 * 8);
            }
            asm volatile("cp.async.commit_group;");
            asm volatile("cp.async.wait_group 1;");
        } else {
            asm volatile("cp.async.wait_group 0;");
        }
        __syncthreads();

        uint32_t sAh = sb + st * GSTG;
        uint32_t sAl = sAh + GOFF_AL;
        uint32_t sBh = sAh + GOFF_BH;
        uint32_t sBl = sAh + GOFF_BL;

#pragma unroll
        for (int k16 = 0; k16 < 4; k16++) {
            int kc = k16 * 16;
            uint32_t bh[4][2], bl[4][2];
#pragma unroll
            for (int j2 = 0; j2 < 2; j2++) {
                int nrow = wn * 32 + j2 * 16 + ((lane >> 4) << 3) + (lane & 7);
                int kcol = kc + (lane & 8);
                uint32_t r[4];
                ldm_x4(r, sBh + nrow * 144 + kcol * 2);
                bh[j2 * 2][0] = r[0]; bh[j2 * 2][1] = r[1];
                bh[j2 * 2 + 1][0] = r[2]; bh[j2 * 2 + 1][1] = r[3];
                ldm_x4(r, sBl + nrow * 144 + kcol * 2);
                bl[j2 * 2][0] = r[0]; bl[j2 * 2][1] = r[1];
                bl[j2 * 2 + 1][0] = r[2]; bl[j2 * 2 + 1][1] = r[3];
            }
            int arow = wm * 16 + (lane & 15);
            int acol = kc + ((lane >> 4) << 3);
            uint32_t ah[4], al[4];
            ldm_x4(ah, sAh + arow * 144 + acol * 2);
            ldm_x4(al, sAl + arow * 144 + acol * 2);
#pragma unroll
            for (int j = 0; j < 4; j++) mma_bf16(acc[j], ah, bh[j]);
#pragma unroll
            for (int j = 0; j < 4; j++) mma_bf16(acc[j], ah, bl[j]);
#pragma unroll
            for (int j = 0; j < 4; j++) mma_bf16(acc[j], al, bh[j]);
        }
        __syncthreads();
    }

    float* outp = g_gpart + (size_t)ks * BB * NG;
    int row0 = wm * 16 + (lane >> 2);
#pragma unroll
    for (int j = 0; j < 4; j++) {
        int col = bn * 128 + wn * 32 + j * 8 + (lane & 3) * 2;
        *(float2*)(outp + (size_t)row0 * NG + col) = make_float2(acc[j][0], acc[j][1]);
        *(float2*)(outp + (size_t)(row0 + 8) * NG + col) = make_float2(acc[j][2], acc[j][3]);
    }
}

// ================= fused step: cell(t) + scores + softmax + ctx(t+1) + X(t+1) =================
// grid = BB blocks x 1024 thr. t = -1 skips the cell phase (h0 = 0 bootstrap).
__global__ __launch_bounds__(1024) void k_step(const float* __restrict__ memory, int t) {
    int b = blockIdx.x;
    int tid = threadIdx.x, wid = tid >> 5, lane = tid & 31;
    __shared__ float hs[HH];
    __shared__ float w[SS];
    __shared__ float red[1024];

    // ---- phase 1: LSTM cell for (b, j=tid) ----
    if (t >= 0) {
        int j = tid;
        size_t pr = ((size_t)b * TT + t) * NG;
        float a0 = g_P[pr + j];
        float a1 = g_P[pr + HH + j];
        float a2 = g_P[pr + 2 * HH + j];
        float a3 = g_P[pr + 3 * HH + j];
#pragma unroll
        for (int z = 0; z < 8; z++) {
            const float* gp = g_gpart + ((size_t)z * BB + b) * NG;
            a0 += gp[j];
            a1 += gp[HH + j];
            a2 += gp[2 * HH + j];
            a3 += gp[3 * HH + j];
        }
        float gi = sigmoidf_(a0);
        float gf = sigmoidf_(a1);
        float gg = tanhf(a2);
        float go = sigmoidf_(a3);
        float cp = g_c[b * HH + j];
        float cn = gf * cp + gi * gg;
        float hn = go * tanhf(cn);
        g_c[b * HH + j] = cn;
        hs[j] = hn;
        __nv_bfloat16 hi, lo;
        bsplit(hn, hi, lo);
        g_Xh[b * KG + HH + j] = hi;
        g_Xl[b * KG + HH + j] = lo;
        size_t ar = ((size_t)b * TT + t) * HH + j;
        g_Ah[ar] = hi;
        g_Al[ar] = lo;
    } else {
        hs[tid] = 0.f;
    }
    __syncthreads();

    // ---- phase 2: scores for step t+1 (32 warps over 196 s, float4) ----
    const float4* hs4 = (const float4*)hs;
    for (int s = wid; s < SS; s += 32) {
        const float4* mr4 = (const float4*)(g_M2 + ((size_t)b * SS + s) * HH);
        float acc = 0.f;
#pragma unroll
        for (int k = 0; k < 2; k++) {
            int k0 = lane + k * 128;
            float4 m0 = mr4[k0],      m1 = mr4[k0 + 32];
            float4 m2 = mr4[k0 + 64], m3 = mr4[k0 + 96];
            float4 h0 = hs4[k0],      h1 = hs4[k0 + 32];
            float4 h2 = hs4[k0 + 64], h3 = hs4[k0 + 96];
            acc += m0.x * h0.x + m0.y * h0.y + m0.z * h0.z + m0.w * h0.w;
            acc += m1.x * h1.x + m1.y * h1.y + m1.z * h1.z + m1.w * h1.w;
            acc += m2.x * h2.x + m2.y * h2.y + m2.z * h2.z + m2.w * h2.w;
            acc += m3.x * h3.x + m3.y * h3.y + m3.z * h3.z + m3.w * h3.w;
        }
#pragma unroll
        for (int o = 16; o > 0; o >>= 1) acc += __shfl_xor_sync(0xffffffffu, acc, o);
        if (lane == 0) w[s] = acc;
    }
    __syncthreads();

    // ---- phase 3: softmax over w[0:196] ----
    float v = (tid < SS) ? w[tid] : -1e30f;
    red[tid] = v;
    __syncthreads();
    for (int o = 512; o > 0; o >>= 1) {
        if (tid < o) red[tid] = fmaxf(red[tid], red[tid + o]);
        __syncthreads();
    }
    float mx = red[0];
    __syncthreads();
    float e = (tid < SS) ? expf(v - mx) : 0.f;
    red[tid] = e;
    __syncthreads();
    if (tid < SS) w[tid] = e;
    for (int o = 512; o > 0; o >>= 1) {
        if (tid < o) red[tid] += red[tid + o];
        __syncthreads();
    }
    float inv = 1.f / red[0];
    __syncthreads();

    // ---- phase 4: ctx, thread = one h-column ----
    const float* mb = memory + (size_t)b * SS * HH + tid;
    float a0 = 0.f, a1 = 0.f, a2 = 0.f, a3 = 0.f;
    int s = 0;
    for (; s + 8 <= SS; s += 8) {
        float m0 = mb[(size_t)(s + 0) * HH], m1 = mb[(size_t)(s + 1) * HH];
        float m2 = mb[(size_t)(s + 2) * HH], m3 = mb[(size_t)(s + 3) * HH];
        float m4 = mb[(size_t)(s + 4) * HH], m5 = mb[(size_t)(s + 5) * HH];
        float m6 = mb[(size_t)(s + 6) * HH], m7 = mb[(size_t)(s + 7) * HH];
        a0 += w[s + 0] * m0; a1 += w[s + 1] * m1; a2 += w[s + 2] * m2; a3 += w[s + 3] * m3;
        a0 += w[s + 4] * m4; a1 += w[s + 5] * m5; a2 += w[s + 6] * m6; a3 += w[s + 7] * m7;
    }
    {
        float m0 = mb[(size_t)(s + 0) * HH], m1 = mb[(size_t)(s + 1) * HH];
        float m2 = mb[(size_t)(s + 2) * HH], m3 = mb[(size_t)(s + 3) * HH];
        a0 += w[s + 0] * m0; a1 += w[s + 1] * m1; a2 += w[s + 2] * m2; a3 += w[s + 3] * m3;
    }
    float cv = (a0 + a1 + a2 + a3) * inv;
    __nv_bfloat16 hi, lo;
    bsplit(cv, hi, lo);
    g_Xh[b * KG + tid] = hi;
    g_Xl[b * KG + tid] = lo;
}

// final cell (t=63)
__global__ void k_cellfin() {
    int i = blockIdx.x * blockDim.x + threadIdx.x;
    int b = i >> 10, j = i & 1023;
    size_t pr = ((size_t)b * TT + 63) * NG;
    float a0 = g_P[pr + j];
    float a1 = g_P[pr + HH + j];
    float a2 = g_P[pr + 2 * HH + j];
    float a3 = g_P[pr + 3 * HH + j];
#pragma unroll
    for (int z = 0; z < 8; z++) {
        const float* gp = g_gpart + ((size_t)z * BB + b) * NG;
        a0 += gp[j];
        a1 += gp[HH + j];
        a2 += gp[2 * HH + j];
        a3 += gp[3 * HH + j];
    }
    float gi = sigmoidf_(a0);
    float gf = sigmoidf_(a1);
    float gg = tanhf(a2);
    float go = sigmoidf_(a3);
    float cn = gf * g_c[i] + gi * gg;
    float hn = go * tanhf(cn);
    g_c[i] = cn;
    g_h[i] = hn;
    __nv_bfloat16 hi, lo;
    bsplit(hn, hi, lo);
    size_t ar = ((size_t)b * TT + 63) * HH + j;
    g_Ah[ar] = hi;
    g_Al[ar] = lo;
}

// ================= output final h, c =================
__global__ void k_final(float* __restrict__ out) {
    int i = blockIdx.x * blockDim.x + threadIdx.x;
    if (i < BB * HH) {
        size_t base = (size_t)BB * TT * VV;
        out[base + i] = g_h[i];
        out[base + BB * HH + i] = g_c[i];
    }
}

// ---------------- launch ----------------
extern "C" void kernel_launch(void* const* d_in, const int* in_sizes, int n_in,
                              void* d_out, int out_size) {
    const float* memory    = (const float*)d_in[0];
    const int*   captions  = (const int*)d_in[1];
    const float* emb_table = (const float*)d_in[2];
    const float* attn_W    = (const float*)d_in[3];
    const float* W_ih      = (const float*)d_in[4];
    const float* W_hh      = (const float*)d_in[5];
    const float* b_ih      = (const float*)d_in[6];
    const float* b_hh      = (const float*)d_in[7];
    const float* W_out     = (const float*)d_in[8];
    const float* b_out     = (const float*)d_in[9];
    float* out = (float*)d_out;

    static int inited = 0;
    if (!inited) {
        cudaFuncSetAttribute(k_gemm_M2, cudaFuncAttributeMaxDynamicSharedMemorySize, LSMEM);
        cudaFuncSetAttribute(k_gemm_P,  cudaFuncAttributeMaxDynamicSharedMemorySize, LSMEM);
        cudaFuncSetAttribute(k_gates_s, cudaFuncAttributeMaxDynamicSharedMemorySize, GSMEM);
        cudaFuncSetAttribute(k_gemm_L,  cudaFuncAttributeMaxDynamicSharedMemorySize, LSMEM);
        inited = 1;
    }

    k_init<<<1024, 256>>>(b_ih, b_hh);
    k_splitW8<<<(int)(((size_t)VV * HH / 8 + 255) / 256), 256>>>(W_out);
    k_splitWg8<<<(int)(((size_t)NG * KG / 8 + 255) / 256), 256>>>(W_ih, W_hh);
    k_splitWihA8<<<(int)(((size_t)NG * HH / 8 + 255) / 256), 256>>>(W_ih);
    k_splitMem8<<<(int)(((size_t)BB * SS * HH / 8 + 255) / 256), 256>>>(memory);
    k_splitEmb8<<<(int)(((size_t)MT * HH / 8 + 255) / 256), 256>>>(captions, emb_table);
    k_splitWt<<<dim3(HH / 32, HH / 32), 256>>>(attn_W);

    k_gemm_M2<<<dim3(BB * SS / 128, HH / 128), 256, LSMEM>>>();
    k_gemm_P<<<dim3(MT / 128, NG / 128), 256, LSMEM>>>();

    k_step<<<BB, 1024>>>(memory, -1);           // ctx(0), X(0)
    for (int t = 0; t < TT; t++) {
        k_gates_s<<<dim3(NG / 128, 8), 256, GSMEM>>>();
        if (t < TT - 1) k_step<<<BB, 1024>>>(memory, t);
        else            k_cellfin<<<128, 256>>>();
    }

    k_gemm_L<<<dim3(MT / 128, VV / 128), 256, LSMEM>>>(b_out, out);
    k_final<<<128, 256>>>(out);
}

// round 13
// speedup vs baseline: 1.3609x; 1.1165x over previous
#include <cuda_runtime.h>
#include <cuda_bf16.h>
#include <cuda_fp16.h>
#include <math.h>
#include <stdint.h>

#define BB 32
#define SS 196
#define TT 64
#define HH 1024
#define VV 32000
#define MT (BB * TT)     // 2048
#define KG 2048          // gates K
#define NG 4096          // gates N

// ---------------- device scratch ----------------
__device__ float g_h[BB * HH];
__device__ float g_c[BB * HH];
__device__ float g_M2[(size_t)BB * SS * HH];
__device__ float g_P[(size_t)MT * NG];
__device__ float g_gpart[(size_t)8 * BB * NG];
__device__ float g_biasg[NG];
__device__ float g_zeroN[VV];
// fp16 operands for 2-pass logits GEMM
__device__ __align__(16) __half g_Whf[(size_t)VV * HH], g_Wlf[(size_t)VV * HH];
__device__ __align__(16) __half g_Af[(size_t)MT * HH];
// bf16 operands for 3-pass recurrence GEMMs
__device__ __align__(16) __nv_bfloat16 g_Memh[(size_t)BB * SS * HH], g_Meml[(size_t)BB * SS * HH];
__device__ __align__(16) __nv_bfloat16 g_Wth[(size_t)HH * HH], g_Wtl[(size_t)HH * HH];
__device__ __align__(16) __nv_bfloat16 g_WihAh[(size_t)NG * HH], g_WihAl[(size_t)NG * HH];
__device__ __align__(16) __nv_bfloat16 g_Wgh[(size_t)NG * KG], g_Wgl[(size_t)NG * KG];
__device__ __align__(16) __nv_bfloat16 g_Embh[(size_t)MT * HH], g_Embl[(size_t)MT * HH];
__device__ __align__(16) __nv_bfloat16 g_Xh[32 * KG], g_Xl[32 * KG];

__device__ __forceinline__ float sigmoidf_(float x) { return 1.f / (1.f + expf(-x)); }
__device__ __forceinline__ void bsplit(float w, __nv_bfloat16& hi, __nv_bfloat16& lo) {
    hi = __float2bfloat16_rn(w);
    lo = __float2bfloat16_rn(w - __bfloat162float(hi));
}
__device__ __forceinline__ void split8(const float* __restrict__ src,
                                       __nv_bfloat16* __restrict__ dh,
                                       __nv_bfloat16* __restrict__ dl) {
    float4 v0 = *(const float4*)src;
    float4 v1 = *(const float4*)(src + 4);
    float f[8] = {v0.x, v0.y, v0.z, v0.w, v1.x, v1.y, v1.z, v1.w};
    __align__(16) __nv_bfloat16 h[8];
    __align__(16) __nv_bfloat16 l[8];
#pragma unroll
    for (int k = 0; k < 8; k++) bsplit(f[k], h[k], l[k]);
    *(uint4*)dh = *(const uint4*)h;
    *(uint4*)dl = *(const uint4*)l;
}
// fp16 hi/lo split, 8-wide
__device__ __forceinline__ void split8h(const float* __restrict__ src,
                                        __half* __restrict__ dh,
                                        __half* __restrict__ dl) {
    float4 v0 = *(const float4*)src;
    float4 v1 = *(const float4*)(src + 4);
    float f[8] = {v0.x, v0.y, v0.z, v0.w, v1.x, v1.y, v1.z, v1.w};
    __align__(16) __half h[8];
    __align__(16) __half l[8];
#pragma unroll
    for (int k = 0; k < 8; k++) {
        __half hi = __float2half_rn(f[k]);
        h[k] = hi;
        l[k] = __float2half_rn(f[k] - __half2float(hi));
    }
    *(uint4*)dh = *(const uint4*)h;
    *(uint4*)dl = *(const uint4*)l;
}

__device__ __forceinline__ uint32_t smem_u32(const void* p) {
    uint32_t a;
    asm("{ .reg .u64 t; cvta.to.shared.u64 t, %1; cvt.u32.u64 %0, t; }" : "=r"(a) : "l"(p));
    return a;
}
__device__ __forceinline__ void cp16(uint32_t s, const void* g) {
    asm volatile("cp.async.cg.shared.global [%0], [%1], 16;" :: "r"(s), "l"(g));
}
__device__ __forceinline__ void ldm_x4(uint32_t* r, uint32_t addr) {
    asm volatile("ldmatrix.sync.aligned.m8n8.x4.shared.b16 {%0,%1,%2,%3}, [%4];"
                 : "=r"(r[0]), "=r"(r[1]), "=r"(r[2]), "=r"(r[3]) : "r"(addr));
}
__device__ __forceinline__ void mma_bf16(float* c, const uint32_t* a, const uint32_t* b) {
    asm volatile("mma.sync.aligned.m16n8k16.row.col.f32.bf16.bf16.f32 "
                 "{%0,%1,%2,%3}, {%4,%5,%6,%7}, {%8,%9}, {%0,%1,%2,%3};"
                 : "+f"(c[0]), "+f"(c[1]), "+f"(c[2]), "+f"(c[3])
                 : "r"(a[0]), "r"(a[1]), "r"(a[2]), "r"(a[3]), "r"(b[0]), "r"(b[1]));
}
__device__ __forceinline__ void mma_f16(float* c, const uint32_t* a, const uint32_t* b) {
    asm volatile("mma.sync.aligned.m16n8k16.row.col.f32.f16.f16.f32 "
                 "{%0,%1,%2,%3}, {%4,%5,%6,%7}, {%8,%9}, {%0,%1,%2,%3};"
                 : "+f"(c[0]), "+f"(c[1]), "+f"(c[2]), "+f"(c[3])
                 : "r"(a[0]), "r"(a[1]), "r"(a[2]), "r"(a[3]), "r"(b[0]), "r"(b[1]));
}

// ================= init / split kernels =================
__global__ void k_init(const float* __restrict__ b_ih, const float* __restrict__ b_hh) {
    int i = blockIdx.x * blockDim.x + threadIdx.x;
    __nv_bfloat16 z = __float2bfloat16(0.f);
    if (i < 32 * KG) { g_Xh[i] = z; g_Xl[i] = z; }
    if (i < BB * HH) { g_h[i] = 0.f; g_c[i] = 0.f; }
    if (i < VV) g_zeroN[i] = 0.f;
    if (i < NG) g_biasg[i] = b_ih[i] + b_hh[i];
}

__global__ void k_splitW8(const float* __restrict__ W) {
    size_t i = ((size_t)blockIdx.x * blockDim.x + threadIdx.x) * 8;
    if (i < (size_t)VV * HH) split8h(W + i, g_Whf + i, g_Wlf + i);
}
__global__ void k_splitWg8(const float* __restrict__ W_ih, const float* __restrict__ W_hh) {
    size_t i = ((size_t)blockIdx.x * blockDim.x + threadIdx.x) * 8;
    if (i < (size_t)NG * KG) {
        size_t n = i >> 11;
        int k = (int)(i & 2047);
        const float* src = (k < HH) ? (W_ih + n * (2 * HH) + HH + k)
                                    : (W_hh + n * HH + (k - HH));
        split8(src, g_Wgh + i, g_Wgl + i);
    }
}
__global__ void k_splitWihA8(const float* __restrict__ W_ih) {
    size_t i = ((size_t)blockIdx.x * blockDim.x + threadIdx.x) * 8;
    if (i < (size_t)NG * HH) {
        size_t n = i >> 10;
        int k = (int)(i & 1023);
        split8(W_ih + n * (2 * HH) + k, g_WihAh + i, g_WihAl + i);
    }
}
__global__ void k_splitMem8(const float* __restrict__ memory) {
    size_t i = ((size_t)blockIdx.x * blockDim.x + threadIdx.x) * 8;
    if (i < (size_t)BB * SS * HH) split8(memory + i, g_Memh + i, g_Meml + i);
}
__global__ void k_splitEmb8(const int* __restrict__ captions, const float* __restrict__ emb_table) {
    size_t i = ((size_t)blockIdx.x * blockDim.x + threadIdx.x) * 8;
    if (i < (size_t)MT * HH) {
        int m = (int)(i >> 10);
        int k = (int)(i & 1023);
        split8(emb_table + (size_t)captions[m] * HH + k, g_Embh + i, g_Embl + i);
    }
}
// Wt[n][j] = attn_W[j][n]
__global__ void k_splitWt(const float* __restrict__ W) {
    __shared__ float tile[32][33];
    int jb = blockIdx.x * 32, nb = blockIdx.y * 32;
    int tx = threadIdx.x & 31, ty = threadIdx.x >> 5;
#pragma unroll
    for (int r = 0; r < 32; r += 8)
        tile[ty + r][tx] = W[(size_t)(jb + ty + r) * HH + nb + tx];
    __syncthreads();
#pragma unroll
    for (int r = 0; r < 32; r += 8) {
        size_t o = (size_t)(nb + ty + r) * HH + jb + tx;
        bsplit(tile[tx][ty + r], g_Wth[o], g_Wtl[o]);
    }
}

// ================= generic 3-pass bf16 HMMA core (BM=BN=128, 256 thr) =================
#define LTILE (128 * 144)           // 18432 B
#define LSTAGE (4 * LTILE)          // 73728 B
#define LSMEM (2 * LSTAGE)          // 147456 B

__device__ __forceinline__ void gemm_core(
    const __nv_bfloat16* __restrict__ Ah, const __nv_bfloat16* __restrict__ Al,
    const __nv_bfloat16* __restrict__ Bh, const __nv_bfloat16* __restrict__ Bl,
    const float* __restrict__ bias, float* __restrict__ out,
    size_t ldout, int Ktot)
{
    extern __shared__ char smem[];
    uint32_t sb = smem_u32(smem);
    int tid = threadIdx.x, wid = tid >> 5, lane = tid & 31;
    int wm = wid >> 2, wn = wid & 3;
    int bm = blockIdx.x, bn = blockIdx.y;
    int chunks = Ktot >> 6;

    const __nv_bfloat16* gA[4];
    gA[0] = Ah + (size_t)bm * 128 * Ktot;
    gA[1] = Al + (size_t)bm * 128 * Ktot;
    gA[2] = Bh + (size_t)bn * 128 * Ktot;
    gA[3] = Bl + (size_t)bn * 128 * Ktot;

    float acc[4][4][4];
#pragma unroll
    for (int i = 0; i < 4; i++)
#pragma unroll
        for (int j = 0; j < 4; j++)
#pragma unroll
            for (int k = 0; k < 4; k++) acc[i][j][k] = 0.f;

    int lrow = tid >> 3, lc4 = tid & 7;

#pragma unroll
    for (int t = 0; t < 4; t++) {
        uint32_t base = sb + t * LTILE;
#pragma unroll
        for (int r4 = 0; r4 < 4; r4++) {
            int row = lrow + r4 * 32;
            cp16(base + row * 144 + lc4 * 16, gA[t] + (size_t)row * Ktot + lc4 * 8);
        }
    }
    asm volatile("cp.async.commit_group;");

    for (int ch = 0; ch < chunks; ch++) {
        int st = ch & 1;
        if (ch < chunks - 1) {
            int k0 = (ch + 1) * 64;
            uint32_t stb = sb + ((ch + 1) & 1) * LSTAGE;
#pragma unroll
            for (int t = 0; t < 4; t++) {
                uint32_t base = stb + t * LTILE;
#pragma unroll
                for (int r4 = 0; r4 < 4; r4++) {
                    int row = lrow + r4 * 32;
                    cp16(base + row * 144 + lc4 * 16, gA[t] + (size_t)row * Ktot + k0 + lc4 * 8);
                }
            }
            asm volatile("cp.async.commit_group;");
            asm volatile("cp.async.wait_group 1;");
        } else {
            asm volatile("cp.async.wait_group 0;");
        }
        __syncthreads();

        uint32_t sAh = sb + st * LSTAGE;
        uint32_t sAl = sAh + LTILE;
        uint32_t sBh = sAh + 2 * LTILE;
        uint32_t sBl = sAh + 3 * LTILE;

#pragma unroll
        for (int k16 = 0; k16 < 4; k16++) {
            int kc = k16 * 16;
            uint32_t bh[4][2], bl[4][2];
#pragma unroll
            for (int j2 = 0; j2 < 2; j2++) {
                int nrow = wn * 32 + j2 * 16 + ((lane >> 4) << 3) + (lane & 7);
                int kcol = kc + (lane & 8);
                uint32_t r[4];
                ldm_x4(r, sBh + nrow * 144 + kcol * 2);
                bh[j2 * 2][0] = r[0]; bh[j2 * 2][1] = r[1];
                bh[j2 * 2 + 1][0] = r[2]; bh[j2 * 2 + 1][1] = r[3];
                ldm_x4(r, sBl + nrow * 144 + kcol * 2);
                bl[j2 * 2][0] = r[0]; bl[j2 * 2][1] = r[1];
                bl[j2 * 2 + 1][0] = r[2]; bl[j2 * 2 + 1][1] = r[3];
            }
#pragma unroll
            for (int i = 0; i < 4; i++) {
                int arow = wm * 64 + i * 16 + (lane & 15);
                int acol = kc + ((lane >> 4) << 3);
                uint32_t ah[4], al[4];
                ldm_x4(ah, sAh + arow * 144 + acol * 2);
                ldm_x4(al, sAl + arow * 144 + acol * 2);
#pragma unroll
                for (int j = 0; j < 4; j++) mma_bf16(acc[i][j], ah, bh[j]);
#pragma unroll
                for (int j = 0; j < 4; j++) mma_bf16(acc[i][j], ah, bl[j]);
#pragma unroll
                for (int j = 0; j < 4; j++) mma_bf16(acc[i][j], al, bh[j]);
            }
        }
        __syncthreads();
    }

#pragma unroll
    for (int i = 0; i < 4; i++) {
        int row0 = bm * 128 + wm * 64 + i * 16 + (lane >> 2);
#pragma unroll
        for (int j = 0; j < 4; j++) {
            int col = bn * 128 + wn * 32 + j * 8 + (lane & 3) * 2;
            float2 bv = *(const float2*)(bias + col);
            *(float2*)(out + (size_t)row0 * ldout + col) =
                make_float2(acc[i][j][0] + bv.x, acc[i][j][1] + bv.y);
            *(float2*)(out + (size_t)(row0 + 8) * ldout + col) =
                make_float2(acc[i][j][2] + bv.x, acc[i][j][3] + bv.y);
        }
    }
}

__global__ __launch_bounds__(256, 1) void k_gemm_M2() {
    gemm_core(g_Memh, g_Meml, g_Wth, g_Wtl, g_zeroN, g_M2, HH, HH);
}
__global__ __launch_bounds__(256, 1) void k_gemm_P() {
    gemm_core(g_Embh, g_Embl, g_WihAh, g_WihAl, g_biasg, g_P, NG, HH);
}

// ================= logits GEMM: 2-pass fp16 (A single, B hi/lo), 3 tiles/stage =================
#define FSTAGE (3 * LTILE)          // 55296
#define FSMEM (2 * FSTAGE)          // 110592 -> 2 blocks/SM

__global__ __launch_bounds__(256, 2) void k_gemm_Lf(const float* __restrict__ bout,
                                                    float* __restrict__ out) {
    extern __shared__ char smem[];
    uint32_t sb = smem_u32(smem);
    int tid = threadIdx.x, wid = tid >> 5, lane = tid & 31;
    int wm = wid >> 2, wn = wid & 3;
    int bm = blockIdx.x, bn = blockIdx.y;

    const __half* gA  = g_Af  + (size_t)bm * 128 * HH;
    const __half* gBh = g_Whf + (size_t)bn * 128 * HH;
    const __half* gBl = g_Wlf + (size_t)bn * 128 * HH;

    float acc[4][4][4];
#pragma unroll
    for (int i = 0; i < 4; i++)
#pragma unroll
        for (int j = 0; j < 4; j++)
#pragma unroll
            for (int k = 0; k < 4; k++) acc[i][j][k] = 0.f;

    int lrow = tid >> 3, lc4 = tid & 7;

#pragma unroll
    for (int r4 = 0; r4 < 4; r4++) {
        int row = lrow + r4 * 32;
        cp16(sb + row * 144 + lc4 * 16, gA + (size_t)row * HH + lc4 * 8);
        cp16(sb + LTILE + row * 144 + lc4 * 16, gBh + (size_t)row * HH + lc4 * 8);
        cp16(sb + 2 * LTILE + row * 144 + lc4 * 16, gBl + (size_t)row * HH + lc4 * 8);
    }
    asm volatile("cp.async.commit_group;");

    for (int ch = 0; ch < 16; ch++) {
        int st = ch & 1;
        if (ch < 15) {
            int k0 = (ch + 1) * 64;
            uint32_t stb = sb + ((ch + 1) & 1) * FSTAGE;
#pragma unroll
            for (int r4 = 0; r4 < 4; r4++) {
                int row = lrow + r4 * 32;
                cp16(stb + row * 144 + lc4 * 16, gA + (size_t)row * HH + k0 + lc4 * 8);
                cp16(stb + LTILE + row * 144 + lc4 * 16, gBh + (size_t)row * HH + k0 + lc4 * 8);
                cp16(stb + 2 * LTILE + row * 144 + lc4 * 16, gBl + (size_t)row * HH + k0 + lc4 * 8);
            }
            asm volatile("cp.async.commit_group;");
            asm volatile("cp.async.wait_group 1;");
        } else {
            asm volatile("cp.async.wait_group 0;");
        }
        __syncthreads();

        uint32_t sA  = sb + st * FSTAGE;
        uint32_t sBh = sA + LTILE;
        uint32_t sBl = sA + 2 * LTILE;

#pragma unroll
        for (int k16 = 0; k16 < 4; k16++) {
            int kc = k16 * 16;
            uint32_t bh[4][2], bl[4][2];
#pragma unroll
            for (int j2 = 0; j2 < 2; j2++) {
                int nrow = wn * 32 + j2 * 16 + ((lane >> 4) << 3) + (lane & 7);
                int kcol = kc + (lane & 8);
                uint32_t r[4];
                ldm_x4(r, sBh + nrow * 144 + kcol * 2);
                bh[j2 * 2][0] = r[0]; bh[j2 * 2][1] = r[1];
                bh[j2 * 2 + 1][0] = r[2]; bh[j2 * 2 + 1][1] = r[3];
                ldm_x4(r, sBl + nrow * 144 + kcol * 2);
                bl[j2 * 2][0] = r[0]; bl[j2 * 2][1] = r[1];
                bl[j2 * 2 + 1][0] = r[2]; bl[j2 * 2 + 1][1] = r[3];
            }
#pragma unroll
            for (int i = 0; i < 4; i++) {
                int arow = wm * 64 + i * 16 + (lane & 15);
                int acol = kc + ((lane >> 4) << 3);
                uint32_t ah[4];
                ldm_x4(ah, sA + arow * 144 + acol * 2);
#pragma unroll
                for (int j = 0; j < 4; j++) mma_f16(acc[i][j], ah, bh[j]);
#pragma unroll
                for (int j = 0; j < 4; j++) mma_f16(acc[i][j], ah, bl[j]);
            }
        }
        __syncthreads();
    }

#pragma unroll
    for (int i = 0; i < 4; i++) {
        int row0 = bm * 128 + wm * 64 + i * 16 + (lane >> 2);
#pragma unroll
        for (int j = 0; j < 4; j++) {
            int col = bn * 128 + wn * 32 + j * 8 + (lane & 3) * 2;
            float2 bv = *(const float2*)(bout + col);
            *(float2*)(out + (size_t)row0 * VV + col) =
                make_float2(acc[i][j][0] + bv.x, acc[i][j][1] + bv.y);
            *(float2*)(out + (size_t)(row0 + 8) * VV + col) =
                make_float2(acc[i][j][2] + bv.x, acc[i][j][3] + bv.y);
        }
    }
}

// ================= gates GEMM: BM=32 (exact M), BN=128, 256 thr, k-split 8 =================
#define GT_A (32 * 144)                 // 4608
#define GT_B (128 * 144)                // 18432
#define GOFF_AL GT_A
#define GOFF_BH (2 * GT_A)
#define GOFF_BL (2 * GT_A + GT_B)
#define GSTG (2 * GT_A + 2 * GT_B)      // 46080
#define GSMEM (2 * GSTG)                // 92160

__global__ __launch_bounds__(256, 2) void k_gates_s() {
    extern __shared__ char smem[];
    uint32_t sb = smem_u32(smem);
    int tid = threadIdx.x, wid = tid >> 5, lane = tid & 31;
    int wm = wid >> 2, wn = wid & 3;     // 2 x 4, warp tile 16x32
    int bn = blockIdx.x, ks = blockIdx.y;
    int kbeg = ks * 256;

    const __nv_bfloat16* gAh = g_Xh + kbeg;
    const __nv_bfloat16* gAl = g_Xl + kbeg;
    const __nv_bfloat16* gBh = g_Wgh + (size_t)bn * 128 * KG + kbeg;
    const __nv_bfloat16* gBl = g_Wgl + (size_t)bn * 128 * KG + kbeg;

    float acc[4][4];
#pragma unroll
    for (int j = 0; j < 4; j++)
#pragma unroll
        for (int k = 0; k < 4; k++) acc[j][k] = 0.f;

    int lrow = tid >> 3, lc4 = tid & 7;  // lrow 0..31

    {
        cp16(sb + lrow * 144 + lc4 * 16, gAh + (size_t)lrow * KG + lc4 * 8);
        cp16(sb + GOFF_AL + lrow * 144 + lc4 * 16, gAl + (size_t)lrow * KG + lc4 * 8);
#pragma unroll
        for (int r4 = 0; r4 < 4; r4++) {
            int row = lrow + r4 * 32;
            cp16(sb + GOFF_BH + row * 144 + lc4 * 16, gBh + (size_t)row * KG + lc4 * 8);
            cp16(sb + GOFF_BL + row * 144 + lc4 * 16, gBl + (size_t)row * KG + lc4 * 8);
        }
        asm volatile("cp.async.commit_group;");
    }

    for (int ch = 0; ch < 4; ch++) {
        int st = ch & 1;
        if (ch < 3) {
            int k0 = (ch + 1) * 64;
            uint32_t stb = sb + ((ch + 1) & 1) * GSTG;
            cp16(stb + lrow * 144 + lc4 * 16, gAh + (size_t)lrow * KG + k0 + lc4 * 8);
            cp16(stb + GOFF_AL + lrow * 144 + lc4 * 16, gAl + (size_t)lrow * KG + k0 + lc4 * 8);
#pragma unroll
            for (int r4 = 0; r4 < 4; r4++) {
                int row = lrow + r4 * 32;
                cp16(stb + GOFF_BH + row * 144 + lc4 * 16, gBh + (size_t)row * KG + k0 + lc4 * 8);
                cp16(stb + GOFF_BL + row * 144 + lc4 * 16, gBl + (size_t)row * KG + k0 + lc4 * 8);
            }
            asm volatile("cp.async.commit_group;");
            asm volatile("cp.async.wait_group 1;");
        } else {
            asm volatile("cp.async.wait_group 0;");
        }
        __syncthreads();

        uint32_t sAh = sb + st * GSTG;
        uint32_t sAl = sAh + GOFF_AL;
        uint32_t sBh = sAh + GOFF_BH;
        uint32_t sBl = sAh + GOFF_BL;

#pragma unroll
        for (int k16 = 0; k16 < 4; k16++) {
            int kc = k16 * 16;
            uint32_t bh[4][2], bl[4][2];
#pragma unroll
            for (int j2 = 0; j2 < 2; j2++) {
                int nrow = wn * 32 + j2 * 16 + ((lane >> 4) << 3) + (lane & 7);
                int kcol = kc + (lane & 8);
                uint32_t r[4];
                ldm_x4(r, sBh + nrow * 144 + kcol * 2);
                bh[j2 * 2][0] = r[0]; bh[j2 * 2][1] = r[1];
                bh[j2 * 2 + 1][0] = r[2]; bh[j2 * 2 + 1][1] = r[3];
                ldm_x4(r, sBl + nrow * 144 + kcol * 2);
                bl[j2 * 2][0] = r[0]; bl[j2 * 2][1] = r[1];
                bl[j2 * 2 + 1][0] = r[2]; bl[j2 * 2 + 1][1] = r[3];
            }
            int arow = wm * 16 + (lane & 15);
            int acol = kc + ((lane >> 4) << 3);
            uint32_t ah[4], al[4];
            ldm_x4(ah, sAh + arow * 144 + acol * 2);
            ldm_x4(al, sAl + arow * 144 + acol * 2);
#pragma unroll
            for (int j = 0; j < 4; j++) mma_bf16(acc[j], ah, bh[j]);
#pragma unroll
            for (int j = 0; j < 4; j++) mma_bf16(acc[j], ah, bl[j]);
#pragma unroll
            for (int j = 0; j < 4; j++) mma_bf16(acc[j], al, bh[j]);
        }
        __syncthreads();
    }

    float* outp = g_gpart + (size_t)ks * BB * NG;
    int row0 = wm * 16 + (lane >> 2);
#pragma unroll
    for (int j = 0; j < 4; j++) {
        int col = bn * 128 + wn * 32 + j * 8 + (lane & 3) * 2;
        *(float2*)(outp + (size_t)row0 * NG + col) = make_float2(acc[j][0], acc[j][1]);
        *(float2*)(outp + (size_t)(row0 + 8) * NG + col) = make_float2(acc[j][2], acc[j][3]);
    }
}

// ================= fused step: cell(t) + scores + softmax + ctx(t+1) + X(t+1) =================
// grid = BB blocks x 1024 thr. t = -1 skips the cell phase (h0 = 0 bootstrap).
__global__ __launch_bounds__(1024) void k_step(const float* __restrict__ memory, int t) {
    int b = blockIdx.x;
    int tid = threadIdx.x, wid = tid >> 5, lane = tid & 31;
    __shared__ float hs[HH];
    __shared__ float w[SS];
    __shared__ float red[1024];

    if (t >= 0) {
        int j = tid;
        size_t pr = ((size_t)b * TT + t) * NG;
        float a0 = g_P[pr + j];
        float a1 = g_P[pr + HH + j];
        float a2 = g_P[pr + 2 * HH + j];
        float a3 = g_P[pr + 3 * HH + j];
#pragma unroll
        for (int z = 0; z < 8; z++) {
            const float* gp = g_gpart + ((size_t)z * BB + b) * NG;
            a0 += gp[j];
            a1 += gp[HH + j];
            a2 += gp[2 * HH + j];
            a3 += gp[3 * HH + j];
        }
        float gi = sigmoidf_(a0);
        float gf = sigmoidf_(a1);
        float gg = tanhf(a2);
        float go = sigmoidf_(a3);
        float cp = g_c[b * HH + j];
        float cn = gf * cp + gi * gg;
        float hn = go * tanhf(cn);
        g_c[b * HH + j] = cn;
        hs[j] = hn;
        __nv_bfloat16 hi, lo;
        bsplit(hn, hi, lo);
        g_Xh[b * KG + HH + j] = hi;
        g_Xl[b * KG + HH + j] = lo;
        g_Af[((size_t)b * TT + t) * HH + j] = __float2half_rn(hn);
    } else {
        hs[tid] = 0.f;
    }
    __syncthreads();

    // scores for step t+1 (32 warps over 196 s, float4)
    const float4* hs4 = (const float4*)hs;
    for (int s = wid; s < SS; s += 32) {
        const float4* mr4 = (const float4*)(g_M2 + ((size_t)b * SS + s) * HH);
        float acc = 0.f;
#pragma unroll
        for (int k = 0; k < 2; k++) {
            int k0 = lane + k * 128;
            float4 m0 = mr4[k0],      m1 = mr4[k0 + 32];
            float4 m2 = mr4[k0 + 64], m3 = mr4[k0 + 96];
            float4 h0 = hs4[k0],      h1 = hs4[k0 + 32];
            float4 h2 = hs4[k0 + 64], h3 = hs4[k0 + 96];
            acc += m0.x * h0.x + m0.y * h0.y + m0.z * h0.z + m0.w * h0.w;
            acc += m1.x * h1.x + m1.y * h1.y + m1.z * h1.z + m1.w * h1.w;
            acc += m2.x * h2.x + m2.y * h2.y + m2.z * h2.z + m2.w * h2.w;
            acc += m3.x * h3.x + m3.y * h3.y + m3.z * h3.z + m3.w * h3.w;
        }
#pragma unroll
        for (int o = 16; o > 0; o >>= 1) acc += __shfl_xor_sync(0xffffffffu, acc, o);
        if (lane == 0) w[s] = acc;
    }
    __syncthreads();

    // softmax over w[0:196]
    float v = (tid < SS) ? w[tid] : -1e30f;
    red[tid] = v;
    __syncthreads();
    for (int o = 512; o > 0; o >>= 1) {
        if (tid < o) red[tid] = fmaxf(red[tid], red[tid + o]);
        __syncthreads();
    }
    float mx = red[0];
    __syncthreads();
    float e = (tid < SS) ? expf(v - mx) : 0.f;
    red[tid] = e;
    __syncthreads();
    if (tid < SS) w[tid] = e;
    for (int o = 512; o > 0; o >>= 1) {
        if (tid < o) red[tid] += red[tid + o];
        __syncthreads();
    }
    float inv = 1.f / red[0];
    __syncthreads();

    // ctx, thread = one h-column
    const float* mb = memory + (size_t)b * SS * HH + tid;
    float a0 = 0.f, a1 = 0.f, a2 = 0.f, a3 = 0.f;
    int s = 0;
    for (; s + 8 <= SS; s += 8) {
        float m0 = mb[(size_t)(s + 0) * HH], m1 = mb[(size_t)(s + 1) * HH];
        float m2 = mb[(size_t)(s + 2) * HH], m3 = mb[(size_t)(s + 3) * HH];
        float m4 = mb[(size_t)(s + 4) * HH], m5 = mb[(size_t)(s + 5) * HH];
        float m6 = mb[(size_t)(s + 6) * HH], m7 = mb[(size_t)(s + 7) * HH];
        a0 += w[s + 0] * m0; a1 += w[s + 1] * m1; a2 += w[s + 2] * m2; a3 += w[s + 3] * m3;
        a0 += w[s + 4] * m4; a1 += w[s + 5] * m5; a2 += w[s + 6] * m6; a3 += w[s + 7] * m7;
    }
    {
        float m0 = mb[(size_t)(s + 0) * HH], m1 = mb[(size_t)(s + 1) * HH];
        float m2 = mb[(size_t)(s + 2) * HH], m3 = mb[(size_t)(s + 3) * HH];
        a0 += w[s + 0] * m0; a1 += w[s + 1] * m1; a2 += w[s + 2] * m2; a3 += w[s + 3] * m3;
    }
    float cv = (a0 + a1 + a2 + a3) * inv;
    __nv_bfloat16 hi, lo;
    bsplit(cv, hi, lo);
    g_Xh[b * KG + tid] = hi;
    g_Xl[b * KG + tid] = lo;
}

// final cell (t=63)
__global__ void k_cellfin() {
    int i = blockIdx.x * blockDim.x + threadIdx.x;
    int b = i >> 10, j = i & 1023;
    size_t pr = ((size_t)b * TT + 63) * NG;
    float a0 = g_P[pr + j];
    float a1 = g_P[pr + HH + j];
    float a2 = g_P[pr + 2 * HH + j];
    float a3 = g_P[pr + 3 * HH + j];
#pragma unroll
    for (int z = 0; z < 8; z++) {
        const float* gp = g_gpart + ((size_t)z * BB + b) * NG;
        a0 += gp[j];
        a1 += gp[HH + j];
        a2 += gp[2 * HH + j];
        a3 += gp[3 * HH + j];
    }
    float gi = sigmoidf_(a0);
    float gf = sigmoidf_(a1);
    float gg = tanhf(a2);
    float go = sigmoidf_(a3);
    float cn = gf * g_c[i] + gi * gg;
    float hn = go * tanhf(cn);
    g_c[i] = cn;
    g_h[i] = hn;
    g_Af[((size_t)b * TT + 63) * HH + j] = __float2half_rn(hn);
}

// ================= output final h, c =================
__global__ void k_final(float* __restrict__ out) {
    int i = blockIdx.x * blockDim.x + threadIdx.x;
    if (i < BB * HH) {
        size_t base = (size_t)BB * TT * VV;
        out[base + i] = g_h[i];
        out[base + BB * HH + i] = g_c[i];
    }
}

// ---------------- launch ----------------
extern "C" void kernel_launch(void* const* d_in, const int* in_sizes, int n_in,
                              void* d_out, int out_size) {
    const float* memory    = (const float*)d_in[0];
    const int*   captions  = (const int*)d_in[1];
    const float* emb_table = (const float*)d_in[2];
    const float* attn_W    = (const float*)d_in[3];
    const float* W_ih      = (const float*)d_in[4];
    const float* W_hh      = (const float*)d_in[5];
    const float* b_ih      = (const float*)d_in[6];
    const float* b_hh      = (const float*)d_in[7];
    const float* W_out     = (const float*)d_in[8];
    const float* b_out     = (const float*)d_in[9];
    float* out = (float*)d_out;

    static int inited = 0;
    if (!inited) {
        cudaFuncSetAttribute(k_gemm_M2, cudaFuncAttributeMaxDynamicSharedMemorySize, LSMEM);
        cudaFuncSetAttribute(k_gemm_P,  cudaFuncAttributeMaxDynamicSharedMemorySize, LSMEM);
        cudaFuncSetAttribute(k_gates_s, cudaFuncAttributeMaxDynamicSharedMemorySize, GSMEM);
        cudaFuncSetAttribute(k_gemm_Lf, cudaFuncAttributeMaxDynamicSharedMemorySize, FSMEM);
        inited = 1;
    }

    k_init<<<1024, 256>>>(b_ih, b_hh);
    k_splitW8<<<(int)(((size_t)VV * HH / 8 + 255) / 256), 256>>>(W_out);
    k_splitWg8<<<(int)(((size_t)NG * KG / 8 + 255) / 256), 256>>>(W_ih, W_hh);
    k_splitWihA8<<<(int)(((size_t)NG * HH / 8 + 255) / 256), 256>>>(W_ih);
    k_splitMem8<<<(int)(((size_t)BB * SS * HH / 8 + 255) / 256), 256>>>(memory);
    k_splitEmb8<<<(int)(((size_t)MT * HH / 8 + 255) / 256), 256>>>(captions, emb_table);
    k_splitWt<<<dim3(HH / 32, HH / 32), 256>>>(attn_W);

    k_gemm_M2<<<dim3(BB * SS / 128, HH / 128), 256, LSMEM>>>();
    k_gemm_P<<<dim3(MT / 128, NG / 128), 256, LSMEM>>>();

    k_step<<<BB, 1024>>>(memory, -1);           // ctx(0), X(0)
    for (int t = 0; t < TT; t++) {
        k_gates_s<<<dim3(NG / 128, 8), 256, GSMEM>>>();
        if (t < TT - 1) k_step<<<BB, 1024>>>(memory, t);
        else            k_cellfin<<<128, 256>>>();
    }

    k_gemm_Lf<<<dim3(MT / 128, VV / 128), 256, FSMEM>>>(b_out, out);
    k_final<<<128, 256>>>(out);
}